// round 3
// baseline (speedup 1.0000x reference)
#include <cuda_runtime.h>
#include <cstdint>

#define DDIM   128
#define MROWS  131072
#define KHALF  (MROWS/2)

// ---------------- device scratch ----------------
__device__ int      g_rowmap_l[MROWS];
__device__ int      g_rowmap_r[MROWS];
__device__ uint32_t g_Bpack[10 * 16384];   // [gate][chunk] pre-swizzled tf32 B fragments

// ---------------- helpers ----------------
__device__ __forceinline__ uint32_t f2tf32(float f) {
    uint32_t r; asm("cvt.rna.tf32.f32 %0, %1;" : "=r"(r) : "f"(f)); return r;
}
__device__ __forceinline__ float ex2f(float x) {
    float y; asm("ex2.approx.f32 %0, %1;" : "=f"(y) : "f"(x)); return y;
}
__device__ __forceinline__ float rcpf(float x) {
    float y; asm("rcp.approx.f32 %0, %1;" : "=f"(y) : "f"(x)); return y;
}
__device__ __forceinline__ float sigf(float x) {   // 1/(1+e^-x), err ~1e-6
    return rcpf(1.0f + ex2f(-1.4426950408889634f * x));
}
__device__ __forceinline__ float tanhf_(float x) { // 2*sig(2x)-1
    return fmaf(2.0f, rcpf(1.0f + ex2f(-2.8853900817779268f * x)), -1.0f);
}

__device__ __forceinline__ void mma_tf32(float* d, const uint32_t* a, const uint32_t* b) {
    asm volatile(
        "mma.sync.aligned.m16n8k8.row.col.f32.tf32.tf32.f32 "
        "{%0,%1,%2,%3}, {%4,%5,%6,%7}, {%8,%9}, {%0,%1,%2,%3};"
        : "+f"(d[0]), "+f"(d[1]), "+f"(d[2]), "+f"(d[3])
        : "r"(a[0]), "r"(a[1]), "r"(a[2]), "r"(a[3]), "r"(b[0]), "r"(b[1]));
}

// ---------------- SMEM layout ----------------
#define SMEM_BIAS  0          // 640 floats
#define SMEM_A     4096       // 128x256 tf32 fragment-packed = 131072 B
#define SMEM_B     135168     // 64KB: B chunk buffer, reused as C tile
#define SMEM_TOTAL 200704

// A pack byte offset for element (r,k):
// cell [mt][kk][lane^ (kk&7)] of 16B holds slots {a0,a1,a2,a3}
__device__ __forceinline__ uint32_t a_off(int r, int k) {
    int mt = r >> 4, kk = k >> 3;
    int lane = ((r & 7) << 2) | (k & 3);
    int slot = ((r >> 3) & 1) | (((k >> 2) & 1) << 1);
    return (uint32_t)((((mt << 5) + kk) << 5) + (lane ^ (kk & 7))) * 16u + (uint32_t)slot * 4u;
}

// C tile (in SMEM_B region): 128 rows x 128 cols fp32, 16B-unit XOR swizzle by row
__device__ __forceinline__ void ct_st2(char* smem, int row, int col, float x, float y) {
    uint32_t byte = SMEM_B + (uint32_t)row * 512u
                  + ((uint32_t)(((col >> 2) ^ (row & 7))) << 4) + (uint32_t)((col & 3) << 2);
    float2 v; v.x = x; v.y = y;
    *(float2*)(smem + byte) = v;
}
__device__ __forceinline__ float4 ct_ld4(const char* smem, int row, int cb) {
    uint32_t byte = SMEM_B + (uint32_t)row * 512u + ((uint32_t)(cb ^ (row & 7)) << 4);
    return *(const float4*)(smem + byte);
}

// ---------------- prep kernels ----------------
__global__ void build_rowmap(const int* __restrict__ bf0, const int* __restrict__ bt0,
                             const int* __restrict__ pf0, const int* __restrict__ pt0,
                             const int* __restrict__ bf1, const int* __restrict__ bt1,
                             const int* __restrict__ pf1, const int* __restrict__ pt1) {
    int i = blockIdx.x * blockDim.x + threadIdx.x;
    if (i >= KHALF) return;
    g_rowmap_l[bt0[i]] = bf0[i];
    g_rowmap_l[pt0[i]] = (int)((uint32_t)pf0[i] | 0x80000000u);
    g_rowmap_r[bt1[i]] = bf1[i];
    g_rowmap_r[pt1[i]] = (int)((uint32_t)pf1[i] | 0x80000000u);
}

// W [256,640] -> per-(gate,chunk) fragment-packed tf32 blocks of 16384 words
__global__ void pack_w(const float* __restrict__ W) {
    int idx = blockIdx.x * blockDim.x + threadIdx.x;
    if (idx >= 256 * 640) return;
    int k = idx / 640, col = idx % 640;
    int gate = col >> 7, n = col & 127;
    int ch = k >> 7, kl = k & 7, kkl = (k & 127) >> 3;
    int nt = n >> 3, nl = n & 7;
    int lane = (nl << 2) | (kl & 3);
    int slot = (kl >> 2) & 1;
    g_Bpack[(gate * 2 + ch) * 16384 + ((((nt << 4) + kkl) << 5) + lane) * 2 + slot] = f2tf32(W[idx]);
}

// ---------------- main fused kernel ----------------
__global__ void __launch_bounds__(256, 1) treelstm_main(
    const float* __restrict__ h_bot, const float* __restrict__ c_bot,
    const float* __restrict__ h_buf, const float* __restrict__ c_buf,
    const float* __restrict__ bias,  float* __restrict__ out) {
    extern __shared__ char smem[];
    float* bias_s = (float*)(smem + SMEM_BIAS);

    const int tid = threadIdx.x, wid = tid >> 5, lane = tid & 31;
    const int g = lane >> 2, tig = lane & 3;
    const int wm = wid & 1;        // M position: 0/1 -> rows 0/64
    const int wn = wid >> 1;       // N position: 0..3 -> cols 0/32/64/96
    const int blk = blockIdx.x;

    for (int t = tid; t < 640; t += 256) bias_s[t] = bias[t];

    // ---- gather X = [h_l | h_r] into fragment-packed A (tf32) ----
    // warp handles one (row, src) per iteration: 32 lanes x float4 = 128 floats
    for (int j = wid; j < 256; j += 8) {
        int src = j & 1, r = j >> 1;
        int m = blk * 128 + r;
        int map = src ? g_rowmap_r[m] : g_rowmap_l[m];
        const float* sp = ((map < 0) ? h_buf : h_bot) + (size_t)(uint32_t)(map & 0x7fffffff) * DDIM;
        float4 v = ((const float4*)sp)[lane];
        int k0 = src * 128 + lane * 4;
        char* ab = smem + SMEM_A;
        *(uint32_t*)(ab + a_off(r, k0 + 0)) = f2tf32(v.x);
        *(uint32_t*)(ab + a_off(r, k0 + 1)) = f2tf32(v.y);
        *(uint32_t*)(ab + a_off(r, k0 + 2)) = f2tf32(v.z);
        *(uint32_t*)(ab + a_off(r, k0 + 3)) = f2tf32(v.w);
    }
    // (first __syncthreads inside the pass loop orders gather before MMA)

    const int r_ep = tid >> 1, half = tid & 1;
    const int m_ep = blk * 128 + r_ep;
    const int map_l = g_rowmap_l[m_ep];
    const int map_r = g_rowmap_r[m_ep];

    float creg[64];
    const int order[5] = {0, 2, 3, 4, 1};   // i, u, f_l, f_r, o

    #pragma unroll 1
    for (int p = 0; p < 5; p++) {
        const int gate = order[p];
        float acc[4][4][4];
        #pragma unroll
        for (int mi = 0; mi < 4; mi++)
            #pragma unroll
            for (int ni = 0; ni < 4; ni++)
                #pragma unroll
                for (int c = 0; c < 4; c++) acc[mi][ni][c] = 0.0f;

        #pragma unroll 1
        for (int ch = 0; ch < 2; ch++) {
            __syncthreads();   // previous C-tile / chunk consumers done
            { // linear copy of pre-packed B chunk (64KB)
                const float4* s = (const float4*)(g_Bpack + (gate * 2 + ch) * 16384);
                float4* d = (float4*)(smem + SMEM_B);
                #pragma unroll
                for (int t = tid; t < 4096; t += 256) d[t] = s[t];
            }
            __syncthreads();

            #pragma unroll 1
            for (int kk = 0; kk < 16; kk++) {
                const int kkg = ch * 16 + kk;
                uint32_t a[4][4], b[4][2];
                #pragma unroll
                for (int mi = 0; mi < 4; mi++) {
                    int mt = wm * 4 + mi;
                    uint4 v = *(const uint4*)(smem + SMEM_A +
                        (uint32_t)((((mt << 5) + kkg) << 5) + (lane ^ (kkg & 7))) * 16u);
                    a[mi][0] = v.x; a[mi][1] = v.y; a[mi][2] = v.z; a[mi][3] = v.w;
                }
                #pragma unroll
                for (int ni = 0; ni < 4; ni++) {
                    int nt = wn * 4 + ni;
                    uint2 v = *(const uint2*)(smem + SMEM_B +
                        (uint32_t)((((nt << 4) + kk) << 5) + lane) * 8u);
                    b[ni][0] = v.x; b[ni][1] = v.y;
                }
                #pragma unroll
                for (int mi = 0; mi < 4; mi++)
                    #pragma unroll
                    for (int ni = 0; ni < 4; ni++)
                        mma_tf32(acc[mi][ni], a[mi], b[ni]);
            }
        }
        __syncthreads();   // all B reads done -> reuse region as C tile

        // ---- store accumulators to C tile ----
        #pragma unroll
        for (int mi = 0; mi < 4; mi++)
            #pragma unroll
            for (int ni = 0; ni < 4; ni++) {
                int row = wm * 64 + mi * 16 + g;
                int col = wn * 32 + ni * 8 + tig * 2;
                ct_st2(smem, row,     col, acc[mi][ni][0], acc[mi][ni][1]);
                ct_st2(smem, row + 8, col, acc[mi][ni][2], acc[mi][ni][3]);
            }
        __syncthreads();

        // ---- fused epilogue: thread owns (row r_ep, 64-col half) ----
        const float* bs = bias_s + gate * 128 + half * 64;
        if (p == 0) {            // i gate
            #pragma unroll
            for (int i = 0; i < 16; i++) {
                float4 d = ct_ld4(smem, r_ep, half * 16 + i);
                creg[i*4+0] = sigf(d.x + bs[i*4+0]);
                creg[i*4+1] = sigf(d.y + bs[i*4+1]);
                creg[i*4+2] = sigf(d.z + bs[i*4+2]);
                creg[i*4+3] = sigf(d.w + bs[i*4+3]);
            }
        } else if (p == 1) {     // u gate
            #pragma unroll
            for (int i = 0; i < 16; i++) {
                float4 d = ct_ld4(smem, r_ep, half * 16 + i);
                creg[i*4+0] *= tanhf_(d.x + bs[i*4+0]);
                creg[i*4+1] *= tanhf_(d.y + bs[i*4+1]);
                creg[i*4+2] *= tanhf_(d.z + bs[i*4+2]);
                creg[i*4+3] *= tanhf_(d.w + bs[i*4+3]);
            }
        } else if (p == 2 || p == 3) {   // f_l / f_r gates
            int map = (p == 2) ? map_l : map_r;
            const float* cp = ((map < 0) ? c_buf : c_bot)
                              + (size_t)(uint32_t)(map & 0x7fffffff) * DDIM + half * 64;
            #pragma unroll
            for (int i = 0; i < 16; i++) {
                float4 d = ct_ld4(smem, r_ep, half * 16 + i);
                float4 cv = ((const float4*)cp)[i];
                creg[i*4+0] = fmaf(sigf(d.x + bs[i*4+0]), cv.x, creg[i*4+0]);
                creg[i*4+1] = fmaf(sigf(d.y + bs[i*4+1]), cv.y, creg[i*4+1]);
                creg[i*4+2] = fmaf(sigf(d.z + bs[i*4+2]), cv.z, creg[i*4+2]);
                creg[i*4+3] = fmaf(sigf(d.w + bs[i*4+3]), cv.w, creg[i*4+3]);
            }
        } else {                 // o gate: finalize and write out
            float* oh = out + (size_t)m_ep * DDIM + half * 64;
            float* oc = out + (size_t)MROWS * DDIM + (size_t)m_ep * DDIM + half * 64;
            #pragma unroll
            for (int i = 0; i < 16; i++) {
                float4 d = ct_ld4(smem, r_ep, half * 16 + i);
                float4 cc, hh;
                cc.x = creg[i*4+0]; hh.x = sigf(d.x + bs[i*4+0]) * tanhf_(cc.x);
                cc.y = creg[i*4+1]; hh.y = sigf(d.y + bs[i*4+1]) * tanhf_(cc.y);
                cc.z = creg[i*4+2]; hh.z = sigf(d.z + bs[i*4+2]) * tanhf_(cc.z);
                cc.w = creg[i*4+3]; hh.w = sigf(d.w + bs[i*4+3]) * tanhf_(cc.w);
                ((float4*)oh)[i] = hh;
                ((float4*)oc)[i] = cc;
            }
        }
    }
}

// ---------------- launch ----------------
extern "C" void kernel_launch(void* const* d_in, const int* in_sizes, int n_in,
                              void* d_out, int out_size) {
    const float* h_bot = (const float*)d_in[0];
    const float* c_bot = (const float*)d_in[1];
    const float* h_buf = (const float*)d_in[2];
    const float* c_buf = (const float*)d_in[3];
    const float* W     = (const float*)d_in[4];
    const float* b     = (const float*)d_in[5];
    const int* bf0 = (const int*)d_in[6];
    const int* bt0 = (const int*)d_in[7];
    const int* pf0 = (const int*)d_in[8];
    const int* pt0 = (const int*)d_in[9];
    const int* bf1 = (const int*)d_in[10];
    const int* bt1 = (const int*)d_in[11];
    const int* pf1 = (const int*)d_in[12];
    const int* pt1 = (const int*)d_in[13];
    float* out = (float*)d_out;

    cudaFuncSetAttribute(treelstm_main, cudaFuncAttributeMaxDynamicSharedMemorySize, SMEM_TOTAL);

    build_rowmap<<<(KHALF + 255) / 256, 256>>>(bf0, bt0, pf0, pt0, bf1, bt1, pf1, pt1);
    pack_w<<<(256 * 640 + 255) / 256, 256>>>(W);
    treelstm_main<<<MROWS / 128, 256, SMEM_TOTAL>>>(h_bot, c_bot, h_buf, c_buf, b, out);
}

// round 4
// speedup vs baseline: 1.2688x; 1.2688x over previous
#include <cuda_runtime.h>
#include <cstdint>

#define DDIM   128
#define MROWS  131072
#define KHALF  (MROWS/2)

// ---------------- device scratch ----------------
__device__ int      g_rowmap_l[MROWS];
__device__ int      g_rowmap_r[MROWS];
// [pass-major] pre-swizzled tf32 B fragments:
//  pass0 {i,u}: words [0, 65536)        8 chunks x 8192 words (2 gate slots)
//  f_l:         words [65536, 98304)    8 chunks x 4096
//  f_r:         words [98304, 131072)
//  o:           words [131072, 163840)
__device__ uint32_t g_Bpack[163840];

// ---------------- helpers ----------------
__device__ __forceinline__ uint32_t smem_u32(const void* p) {
    uint32_t a;
    asm("{ .reg .u64 t; cvta.to.shared.u64 t, %1; cvt.u32.u64 %0, t; }" : "=r"(a) : "l"(p));
    return a;
}
__device__ __forceinline__ uint32_t f2tf32(float f) {
    uint32_t r; asm("cvt.rna.tf32.f32 %0, %1;" : "=r"(r) : "f"(f)); return r;
}
__device__ __forceinline__ float ex2f(float x) {
    float y; asm("ex2.approx.f32 %0, %1;" : "=f"(y) : "f"(x)); return y;
}
__device__ __forceinline__ float rcpf(float x) {
    float y; asm("rcp.approx.f32 %0, %1;" : "=f"(y) : "f"(x)); return y;
}
__device__ __forceinline__ float sigf(float x) {
    return rcpf(1.0f + ex2f(-1.4426950408889634f * x));
}
__device__ __forceinline__ float tanhf_(float x) {
    return fmaf(2.0f, rcpf(1.0f + ex2f(-2.8853900817779268f * x)), -1.0f);
}
__device__ __forceinline__ void mma_tf32(float* d, const uint32_t* a, const uint32_t* b) {
    asm volatile(
        "mma.sync.aligned.m16n8k8.row.col.f32.tf32.tf32.f32 "
        "{%0,%1,%2,%3}, {%4,%5,%6,%7}, {%8,%9}, {%0,%1,%2,%3};"
        : "+f"(d[0]), "+f"(d[1]), "+f"(d[2]), "+f"(d[3])
        : "r"(a[0]), "r"(a[1]), "r"(a[2]), "r"(a[3]), "r"(b[0]), "r"(b[1]));
}
__device__ __forceinline__ void cpa16(uint32_t dst, const uint32_t* src) {
    asm volatile("cp.async.cg.shared.global [%0], [%1], 16;" :: "r"(dst), "l"(src));
}
__device__ __forceinline__ void cp_commit() {
    asm volatile("cp.async.commit_group;" ::: "memory");
}

// ---------------- SMEM layout ----------------
#define SMEM_BIAS  0          // 640 floats = 2560 B
#define SMEM_MAPL  2560       // 128 ints
#define SMEM_MAPR  3072       // 128 ints
#define SMEM_A     4096       // 128x256 tf32 fragment-packed = 131072 B
#define SMEM_B0    135168     // 32 KB
#define SMEM_B1    167936     // 32 KB
#define SMEM_TOTAL 200704

// A pack byte offset (relative to SMEM_A) for element (r,k)
__device__ __forceinline__ uint32_t a_off(int r, int k) {
    int mt = r >> 4, kk = k >> 3;
    int lane = ((r & 7) << 2) | (k & 3);
    int slot = ((r >> 3) & 1) | (((k >> 2) & 1) << 1);
    return (uint32_t)((((mt << 5) + kk) << 5) + (lane ^ (kk & 7))) * 16u + (uint32_t)slot * 4u;
}

// ---------------- prep kernels ----------------
__global__ void build_rowmap(const int* __restrict__ bf0, const int* __restrict__ bt0,
                             const int* __restrict__ pf0, const int* __restrict__ pt0,
                             const int* __restrict__ bf1, const int* __restrict__ bt1,
                             const int* __restrict__ pf1, const int* __restrict__ pt1) {
    int i = blockIdx.x * blockDim.x + threadIdx.x;
    if (i >= KHALF) return;
    g_rowmap_l[bt0[i]] = bf0[i];
    g_rowmap_l[pt0[i]] = (int)((uint32_t)pf0[i] | 0x80000000u);
    g_rowmap_r[bt1[i]] = bf1[i];
    g_rowmap_r[pt1[i]] = (int)((uint32_t)pf1[i] | 0x80000000u);
}

// W [256,640] row-major -> pass-major fragment layout (see g_Bpack comment)
// gate index by column block: 0:i 1:o 2:u 3:f_l 4:f_r
__global__ void pack_w(const float* __restrict__ W) {
    int idx = blockIdx.x * blockDim.x + threadIdx.x;
    if (idx >= 256 * 640) return;
    int k = idx / 640, col = idx % 640;
    int gate = col >> 7, n = col & 127;
    int base, slot, cstride;
    if      (gate == 0) { base = 0;      slot = 0; cstride = 8192; }
    else if (gate == 2) { base = 0;      slot = 1; cstride = 8192; }
    else if (gate == 3) { base = 65536;  slot = 0; cstride = 4096; }
    else if (gate == 4) { base = 98304;  slot = 0; cstride = 4096; }
    else                { base = 131072; slot = 0; cstride = 4096; }   // o
    int nt = n >> 3, nl = n & 7;
    int chunk = k >> 5, kk = (k >> 3) & 3, kl = k & 7;
    int lane = (nl << 2) | (kl & 3);
    int ws = (kl >> 2) & 1;
    int off = base + chunk * cstride + slot * 4096
            + ((kk * 8 + (nt >> 1)) * 32 + lane) * 4 + (nt & 1) * 2 + ws;
    g_Bpack[off] = f2tf32(W[idx]);
}

// ---------------- pipelined MMA pass ----------------
template<int NS>
__device__ __forceinline__ void issue_chunk(uint32_t sdst, const uint32_t* src, int tid) {
    #pragma unroll
    for (int i = 0; i < NS * 4; i++) {
        int unit = i * 256 + tid;
        cpa16(sdst + (uint32_t)unit * 16u, src + unit * 4);
    }
    cp_commit();
}

template<int NS>
__device__ __forceinline__ void run_pass(const uint32_t* __restrict__ gW,
                                         char* smem, uint32_t sbase,
                                         int tid, int wm, int wq, int lane,
                                         float acc[][4][4][4], bool preloaded) {
    #pragma unroll
    for (int s = 0; s < NS; s++)
        #pragma unroll
        for (int mi = 0; mi < 4; mi++)
            #pragma unroll
            for (int ni = 0; ni < 4; ni++)
                #pragma unroll
                for (int c = 0; c < 4; c++) acc[s][mi][ni][c] = 0.0f;

    const int CW = NS * 4096;   // words per chunk
    if (!preloaded) issue_chunk<NS>(sbase + SMEM_B0, gW, tid);

    #pragma unroll 1
    for (int c = 0; c < 8; c++) {
        if (c < 7) {
            issue_chunk<NS>(sbase + ((c & 1) ? SMEM_B0 : SMEM_B1), gW + (c + 1) * CW, tid);
            asm volatile("cp.async.wait_group 1;" ::: "memory");
        } else {
            asm volatile("cp.async.wait_group 0;" ::: "memory");
        }
        __syncthreads();
        const char* bb = smem + ((c & 1) ? SMEM_B1 : SMEM_B0);

        #pragma unroll 1
        for (int kk = 0; kk < 4; kk++) {
            const int kkg = c * 4 + kk;
            uint32_t a[4][4];
            #pragma unroll
            for (int mi = 0; mi < 4; mi++) {
                uint4 v = *(const uint4*)(smem + SMEM_A +
                    (uint32_t)((((wm * 4 + mi) * 32 + kkg) * 32) + (lane ^ (kkg & 7))) * 16u);
                a[mi][0] = v.x; a[mi][1] = v.y; a[mi][2] = v.z; a[mi][3] = v.w;
            }
            uint32_t b[NS][4][2];
            #pragma unroll
            for (int s = 0; s < NS; s++)
                #pragma unroll
                for (int np2 = 0; np2 < 2; np2++) {
                    uint4 v = *(const uint4*)(bb + s * 16384 +
                        (uint32_t)(((kk * 8 + wq * 2 + np2) * 32) + lane) * 16u);
                    b[s][np2 * 2][0]     = v.x; b[s][np2 * 2][1]     = v.y;
                    b[s][np2 * 2 + 1][0] = v.z; b[s][np2 * 2 + 1][1] = v.w;
                }
            #pragma unroll
            for (int s = 0; s < NS; s++)
                #pragma unroll
                for (int mi = 0; mi < 4; mi++)
                    #pragma unroll
                    for (int ni = 0; ni < 4; ni++)
                        mma_tf32(acc[s][mi][ni], a[mi], b[s][ni]);
        }
        __syncthreads();
    }
}

// ---------------- fused epilogue pieces ----------------
__device__ __forceinline__ void ep_forget(const float acc[4][4][4], float creg[4][4][4],
                                          const int* maps, const float* c_bot, const float* c_buf,
                                          const float* bias_g, int wm, int wq, int g, int tig) {
    #pragma unroll
    for (int mi = 0; mi < 4; mi++) {
        int row0 = wm * 64 + mi * 16 + g;
        int mp0 = maps[row0], mp1 = maps[row0 + 8];
        const float* cp0 = ((mp0 < 0) ? c_buf : c_bot) + (size_t)(uint32_t)(mp0 & 0x7fffffff) * DDIM;
        const float* cp1 = ((mp1 < 0) ? c_buf : c_bot) + (size_t)(uint32_t)(mp1 & 0x7fffffff) * DDIM;
        #pragma unroll
        for (int ni = 0; ni < 4; ni++) {
            int colg = wq * 32 + ni * 8 + tig * 2;
            float2 bf  = *(const float2*)(bias_g + colg);
            float2 cv0 = *(const float2*)(cp0 + colg);
            float2 cv1 = *(const float2*)(cp1 + colg);
            creg[mi][ni][0] = fmaf(sigf(acc[mi][ni][0] + bf.x), cv0.x, creg[mi][ni][0]);
            creg[mi][ni][1] = fmaf(sigf(acc[mi][ni][1] + bf.y), cv0.y, creg[mi][ni][1]);
            creg[mi][ni][2] = fmaf(sigf(acc[mi][ni][2] + bf.x), cv1.x, creg[mi][ni][2]);
            creg[mi][ni][3] = fmaf(sigf(acc[mi][ni][3] + bf.y), cv1.y, creg[mi][ni][3]);
        }
    }
}

// ---------------- main fused kernel ----------------
__global__ void __launch_bounds__(256, 1) treelstm_main(
    const float* __restrict__ h_bot, const float* __restrict__ c_bot,
    const float* __restrict__ h_buf, const float* __restrict__ c_buf,
    const float* __restrict__ bias,  float* __restrict__ out) {
    extern __shared__ char smem[];
    const uint32_t sbase = smem_u32(smem);
    float* bias_s = (float*)(smem + SMEM_BIAS);
    int*   mapl_s = (int*)(smem + SMEM_MAPL);
    int*   mapr_s = (int*)(smem + SMEM_MAPR);

    const int tid = threadIdx.x, wid = tid >> 5, lane = tid & 31;
    const int g = lane >> 2, tig = lane & 3;
    const int wm = wid & 1, wq = wid >> 1;
    const int blk = blockIdx.x;

    // preload pass0 chunk0 so its latency hides under the A gather
    issue_chunk<2>(sbase + SMEM_B0, g_Bpack, tid);

    for (int t = tid; t < 640; t += 256) bias_s[t] = bias[t];
    if (tid < 128) {
        mapl_s[tid] = g_rowmap_l[blk * 128 + tid];
        mapr_s[tid] = g_rowmap_r[blk * 128 + tid];
    }

    // ---- gather X = [h_l | h_r] into fragment-packed A (tf32) ----
    for (int j = wid; j < 256; j += 8) {
        int src = j & 1, r = j >> 1;
        int m = blk * 128 + r;
        int map = src ? g_rowmap_r[m] : g_rowmap_l[m];
        const float* sp = ((map < 0) ? h_buf : h_bot) + (size_t)(uint32_t)(map & 0x7fffffff) * DDIM;
        float4 v = ((const float4*)sp)[lane];
        int k0 = src * 128 + lane * 4;
        char* ab = smem + SMEM_A;
        *(uint32_t*)(ab + a_off(r, k0 + 0)) = f2tf32(v.x);
        *(uint32_t*)(ab + a_off(r, k0 + 1)) = f2tf32(v.y);
        *(uint32_t*)(ab + a_off(r, k0 + 2)) = f2tf32(v.z);
        *(uint32_t*)(ab + a_off(r, k0 + 3)) = f2tf32(v.w);
    }
    // first __syncthreads inside run_pass orders gather/maps before use

    float acc[2][4][4][4];
    float creg[4][4][4];

    // ---- pass 0: gates i & u together ----
    run_pass<2>(g_Bpack, smem, sbase, tid, wm, wq, lane, acc, true);
    #pragma unroll
    for (int mi = 0; mi < 4; mi++)
        #pragma unroll
        for (int ni = 0; ni < 4; ni++) {
            int colg = wq * 32 + ni * 8 + tig * 2;
            float2 bi = *(const float2*)(bias_s + colg);         // gate i cols 0..127
            float2 bu = *(const float2*)(bias_s + 256 + colg);   // gate u cols 256..383
            creg[mi][ni][0] = sigf(acc[0][mi][ni][0] + bi.x) * tanhf_(acc[1][mi][ni][0] + bu.x);
            creg[mi][ni][1] = sigf(acc[0][mi][ni][1] + bi.y) * tanhf_(acc[1][mi][ni][1] + bu.y);
            creg[mi][ni][2] = sigf(acc[0][mi][ni][2] + bi.x) * tanhf_(acc[1][mi][ni][2] + bu.x);
            creg[mi][ni][3] = sigf(acc[0][mi][ni][3] + bi.y) * tanhf_(acc[1][mi][ni][3] + bu.y);
        }

    // ---- pass 1: f_l ----
    run_pass<1>(g_Bpack + 65536, smem, sbase, tid, wm, wq, lane, acc, false);
    ep_forget(acc[0], creg, mapl_s, c_bot, c_buf, bias_s + 384, wm, wq, g, tig);

    // ---- pass 2: f_r ----
    run_pass<1>(g_Bpack + 98304, smem, sbase, tid, wm, wq, lane, acc, false);
    ep_forget(acc[0], creg, mapr_s, c_bot, c_buf, bias_s + 512, wm, wq, g, tig);

    // ---- pass 3: o -> finalize h, c ----
    run_pass<1>(g_Bpack + 131072, smem, sbase, tid, wm, wq, lane, acc, false);
    #pragma unroll
    for (int mi = 0; mi < 4; mi++) {
        int row0 = wm * 64 + mi * 16 + g;
        size_t m0 = (size_t)(blk * 128 + row0);
        size_t m1 = m0 + 8;
        #pragma unroll
        for (int ni = 0; ni < 4; ni++) {
            int colg = wq * 32 + ni * 8 + tig * 2;
            float2 bo = *(const float2*)(bias_s + 128 + colg);   // gate o cols 128..255
            float2 h0, h1, c0, c1;
            c0.x = creg[mi][ni][0]; h0.x = sigf(acc[0][mi][ni][0] + bo.x) * tanhf_(c0.x);
            c0.y = creg[mi][ni][1]; h0.y = sigf(acc[0][mi][ni][1] + bo.y) * tanhf_(c0.y);
            c1.x = creg[mi][ni][2]; h1.x = sigf(acc[0][mi][ni][2] + bo.x) * tanhf_(c1.x);
            c1.y = creg[mi][ni][3]; h1.y = sigf(acc[0][mi][ni][3] + bo.y) * tanhf_(c1.y);
            *(float2*)(out + m0 * DDIM + colg) = h0;
            *(float2*)(out + m1 * DDIM + colg) = h1;
            *(float2*)(out + (size_t)MROWS * DDIM + m0 * DDIM + colg) = c0;
            *(float2*)(out + (size_t)MROWS * DDIM + m1 * DDIM + colg) = c1;
        }
    }
}

// ---------------- launch ----------------
extern "C" void kernel_launch(void* const* d_in, const int* in_sizes, int n_in,
                              void* d_out, int out_size) {
    const float* h_bot = (const float*)d_in[0];
    const float* c_bot = (const float*)d_in[1];
    const float* h_buf = (const float*)d_in[2];
    const float* c_buf = (const float*)d_in[3];
    const float* W     = (const float*)d_in[4];
    const float* b     = (const float*)d_in[5];
    const int* bf0 = (const int*)d_in[6];
    const int* bt0 = (const int*)d_in[7];
    const int* pf0 = (const int*)d_in[8];
    const int* pt0 = (const int*)d_in[9];
    const int* bf1 = (const int*)d_in[10];
    const int* bt1 = (const int*)d_in[11];
    const int* pf1 = (const int*)d_in[12];
    const int* pt1 = (const int*)d_in[13];
    float* out = (float*)d_out;

    cudaFuncSetAttribute(treelstm_main, cudaFuncAttributeMaxDynamicSharedMemorySize, SMEM_TOTAL);

    build_rowmap<<<(KHALF + 255) / 256, 256>>>(bf0, bt0, pf0, pt0, bf1, bt1, pf1, pt1);
    pack_w<<<(256 * 640 + 255) / 256, 256>>>(W);
    treelstm_main<<<MROWS / 128, 256, SMEM_TOTAL>>>(h_bot, c_bot, h_buf, c_buf, b, out);
}

// round 5
// speedup vs baseline: 1.3379x; 1.0545x over previous
#include <cuda_runtime.h>
#include <cstdint>

#define DDIM   128
#define MROWS  131072
#define KHALF  (MROWS/2)

// ---------------- device scratch ----------------
__device__ int      g_rowmap_l[MROWS];
__device__ int      g_rowmap_r[MROWS];
// pass-major pre-swizzled tf32 B fragments (uniform 8192-word = 32KB chunks):
//  pass0 {i,u}:    words [0,      65536)  8 chunks (K=32 each, 2 gate slots)
//  pass1 {fl,fr}:  words [65536, 131072)  8 chunks (K=32 each, 2 gate slots)
//  pass2 {o}:      words [131072,163840)  4 chunks (K=64 each, 1 slot)
__device__ uint32_t g_Bpack[163840];

// ---------------- helpers ----------------
__device__ __forceinline__ uint32_t smem_u32(const void* p) {
    uint32_t a;
    asm("{ .reg .u64 t; cvta.to.shared.u64 t, %1; cvt.u32.u64 %0, t; }" : "=r"(a) : "l"(p));
    return a;
}
__device__ __forceinline__ uint32_t f2tf32(float f) {
    uint32_t r; asm("cvt.rna.tf32.f32 %0, %1;" : "=r"(r) : "f"(f)); return r;
}
__device__ __forceinline__ float ex2f(float x) {
    float y; asm("ex2.approx.f32 %0, %1;" : "=f"(y) : "f"(x)); return y;
}
__device__ __forceinline__ float rcpf(float x) {
    float y; asm("rcp.approx.f32 %0, %1;" : "=f"(y) : "f"(x)); return y;
}
__device__ __forceinline__ float sigf(float x) {
    return rcpf(1.0f + ex2f(-1.4426950408889634f * x));
}
__device__ __forceinline__ float tanhf_(float x) {
    return fmaf(2.0f, rcpf(1.0f + ex2f(-2.8853900817779268f * x)), -1.0f);
}
__device__ __forceinline__ void mma_tf32(float* d, const uint32_t* a, const uint32_t* b) {
    asm volatile(
        "mma.sync.aligned.m16n8k8.row.col.f32.tf32.tf32.f32 "
        "{%0,%1,%2,%3}, {%4,%5,%6,%7}, {%8,%9}, {%0,%1,%2,%3};"
        : "+f"(d[0]), "+f"(d[1]), "+f"(d[2]), "+f"(d[3])
        : "r"(a[0]), "r"(a[1]), "r"(a[2]), "r"(a[3]), "r"(b[0]), "r"(b[1]));
}
__device__ __forceinline__ void cpa16(uint32_t dst, const uint32_t* src) {
    asm volatile("cp.async.cg.shared.global [%0], [%1], 16;" :: "r"(dst), "l"(src));
}
__device__ __forceinline__ void cp_commit() {
    asm volatile("cp.async.commit_group;" ::: "memory");
}

// ---------------- SMEM layout ----------------
#define SMEM_BIAS  0          // 640 floats = 2560 B
#define SMEM_MAPL  2560       // 128 ints
#define SMEM_MAPR  3072       // 128 ints
#define SMEM_A     4096       // 128x256 tf32 fragment-packed = 131072 B
#define SMEM_B0    135168     // 32 KB
#define SMEM_B1    167936     // 32 KB
#define SMEM_TOTAL 200704

// A pack byte offset (relative to SMEM_A) for element (r,k)
__device__ __forceinline__ uint32_t a_off(int r, int k) {
    int mt = r >> 4, kk = k >> 3;
    int lane = ((r & 7) << 2) | (k & 3);
    int slot = ((r >> 3) & 1) | (((k >> 2) & 1) << 1);
    return (uint32_t)((((mt << 5) + kk) << 5) + (lane ^ (kk & 7))) * 16u + (uint32_t)slot * 4u;
}

// ---------------- prep kernels ----------------
__global__ void build_rowmap(const int* __restrict__ bf0, const int* __restrict__ bt0,
                             const int* __restrict__ pf0, const int* __restrict__ pt0,
                             const int* __restrict__ bf1, const int* __restrict__ bt1,
                             const int* __restrict__ pf1, const int* __restrict__ pt1) {
    int i = blockIdx.x * blockDim.x + threadIdx.x;
    if (i >= KHALF) return;
    g_rowmap_l[bt0[i]] = bf0[i];
    g_rowmap_l[pt0[i]] = (int)((uint32_t)pf0[i] | 0x80000000u);
    g_rowmap_r[bt1[i]] = bf1[i];
    g_rowmap_r[pt1[i]] = (int)((uint32_t)pf1[i] | 0x80000000u);
}

// W [256,640] row-major -> pass-major fragment layout (see g_Bpack comment)
// column blocks of 128: 0:i 1:o 2:u 3:f_l 4:f_r
__global__ void pack_w(const float* __restrict__ W) {
    int idx = blockIdx.x * blockDim.x + threadIdx.x;
    if (idx >= 256 * 640) return;
    int k = idx / 640, col = idx % 640;
    int gate = col >> 7, n = col & 127;
    int pass, slot;
    if      (gate == 0) { pass = 0; slot = 0; }   // i
    else if (gate == 2) { pass = 0; slot = 1; }   // u
    else if (gate == 3) { pass = 1; slot = 0; }   // f_l
    else if (gate == 4) { pass = 1; slot = 1; }   // f_r
    else                { pass = 2; slot = 0; }   // o
    int nt = n >> 3, nl = n & 7;
    int kl = k & 7;
    int lane = (nl << 2) | (kl & 3);
    int ws = (kl >> 2) & 1;
    int off;
    if (pass < 2) {  // K-chunk 32, 2 slots
        int chunk = k >> 5, kk = (k >> 3) & 3;
        off = pass * 65536 + chunk * 8192 + slot * 4096
            + ((kk * 8 + (nt >> 1)) * 32 + lane) * 4 + (nt & 1) * 2 + ws;
    } else {         // K-chunk 64, 1 slot
        int chunk = k >> 6, kk = (k >> 3) & 7;
        off = 131072 + chunk * 8192
            + ((kk * 8 + (nt >> 1)) * 32 + lane) * 4 + (nt & 1) * 2 + ws;
    }
    g_Bpack[off] = f2tf32(W[idx]);
}

// ---------------- pipelined MMA pass ----------------
__device__ __forceinline__ void issue_chunk32(uint32_t sdst, const uint32_t* src, int tid) {
    #pragma unroll
    for (int i = 0; i < 8; i++) {
        int unit = i * 256 + tid;
        cpa16(sdst + (uint32_t)unit * 16u, src + unit * 4);
    }
    cp_commit();
}

// NS gate slots per chunk, NCH chunks, KS k8-steps per chunk (NS*KS == 8)
template<int NS, int NCH, int KS>
__device__ __forceinline__ void run_pass(const uint32_t* __restrict__ gW,
                                         char* smem, uint32_t sbase,
                                         int tid, int wm, int wq, int lane,
                                         float acc[][4][4][4], bool preloaded) {
    #pragma unroll
    for (int s = 0; s < NS; s++)
        #pragma unroll
        for (int mi = 0; mi < 4; mi++)
            #pragma unroll
            for (int ni = 0; ni < 4; ni++)
                #pragma unroll
                for (int c = 0; c < 4; c++) acc[s][mi][ni][c] = 0.0f;

    if (!preloaded) issue_chunk32(sbase + SMEM_B0, gW, tid);

    #pragma unroll 1
    for (int c = 0; c < NCH; c++) {
        if (c < NCH - 1) {
            issue_chunk32(sbase + ((c & 1) ? SMEM_B0 : SMEM_B1), gW + (c + 1) * 8192, tid);
            asm volatile("cp.async.wait_group 1;" ::: "memory");
        } else {
            asm volatile("cp.async.wait_group 0;" ::: "memory");
        }
        __syncthreads();
        const char* bb = smem + ((c & 1) ? SMEM_B1 : SMEM_B0);

        #pragma unroll 1
        for (int kk = 0; kk < KS; kk++) {
            const int kkg = c * KS + kk;
            uint32_t a[4][4];
            #pragma unroll
            for (int mi = 0; mi < 4; mi++) {
                uint4 v = *(const uint4*)(smem + SMEM_A +
                    (uint32_t)((((wm * 4 + mi) * 32 + kkg) * 32) + (lane ^ (kkg & 7))) * 16u);
                a[mi][0] = v.x; a[mi][1] = v.y; a[mi][2] = v.z; a[mi][3] = v.w;
            }
            uint32_t b[NS][4][2];
            #pragma unroll
            for (int s = 0; s < NS; s++)
                #pragma unroll
                for (int np2 = 0; np2 < 2; np2++) {
                    uint4 v = *(const uint4*)(bb + s * 16384 +
                        (uint32_t)(((kk * 8 + wq * 2 + np2) * 32) + lane) * 16u);
                    b[s][np2 * 2][0]     = v.x; b[s][np2 * 2][1]     = v.y;
                    b[s][np2 * 2 + 1][0] = v.z; b[s][np2 * 2 + 1][1] = v.w;
                }
            #pragma unroll
            for (int s = 0; s < NS; s++)
                #pragma unroll
                for (int mi = 0; mi < 4; mi++)
                    #pragma unroll
                    for (int ni = 0; ni < 4; ni++)
                        mma_tf32(acc[s][mi][ni], a[mi], b[s][ni]);
        }
        __syncthreads();
    }
}

// ---------------- main fused kernel ----------------
__global__ void __launch_bounds__(256, 1) treelstm_main(
    const float* __restrict__ h_bot, const float* __restrict__ c_bot,
    const float* __restrict__ h_buf, const float* __restrict__ c_buf,
    const float* __restrict__ bias,  float* __restrict__ out) {
    extern __shared__ char smem[];
    const uint32_t sbase = smem_u32(smem);
    float* bias_s = (float*)(smem + SMEM_BIAS);
    int*   mapl_s = (int*)(smem + SMEM_MAPL);
    int*   mapr_s = (int*)(smem + SMEM_MAPR);

    const int tid = threadIdx.x, wid = tid >> 5, lane = tid & 31;
    const int g = lane >> 2, tig = lane & 3;
    const int wm = wid & 1, wq = wid >> 1;
    const int blk = blockIdx.x;

    // preload pass0 chunk0 so its latency hides under the A gather
    issue_chunk32(sbase + SMEM_B0, g_Bpack, tid);

    for (int t = tid; t < 640; t += 256) bias_s[t] = bias[t];
    if (tid < 128) {
        mapl_s[tid] = g_rowmap_l[blk * 128 + tid];
        mapr_s[tid] = g_rowmap_r[blk * 128 + tid];
    }

    // ---- gather X = [h_l | h_r] into fragment-packed A (tf32) ----
    for (int j = wid; j < 256; j += 8) {
        int src = j & 1, r = j >> 1;
        int m = blk * 128 + r;
        int map = src ? g_rowmap_r[m] : g_rowmap_l[m];
        const float* sp = ((map < 0) ? h_buf : h_bot) + (size_t)(uint32_t)(map & 0x7fffffff) * DDIM;
        float4 v = ((const float4*)sp)[lane];
        int k0 = src * 128 + lane * 4;
        char* ab = smem + SMEM_A;
        *(uint32_t*)(ab + a_off(r, k0 + 0)) = f2tf32(v.x);
        *(uint32_t*)(ab + a_off(r, k0 + 1)) = f2tf32(v.y);
        *(uint32_t*)(ab + a_off(r, k0 + 2)) = f2tf32(v.z);
        *(uint32_t*)(ab + a_off(r, k0 + 3)) = f2tf32(v.w);
    }
    // first __syncthreads inside run_pass orders gather/maps before use

    float acc[2][4][4][4];
    float creg[4][4][4];

    // ---- pass 0: gates i & u ----
    run_pass<2, 8, 4>(g_Bpack, smem, sbase, tid, wm, wq, lane, acc, true);
    #pragma unroll
    for (int mi = 0; mi < 4; mi++)
        #pragma unroll
        for (int ni = 0; ni < 4; ni++) {
            int colg = wq * 32 + ni * 8 + tig * 2;
            float2 bi = *(const float2*)(bias_s + colg);         // i: cols 0..127
            float2 bu = *(const float2*)(bias_s + 256 + colg);   // u: cols 256..383
            creg[mi][ni][0] = sigf(acc[0][mi][ni][0] + bi.x) * tanhf_(acc[1][mi][ni][0] + bu.x);
            creg[mi][ni][1] = sigf(acc[0][mi][ni][1] + bi.y) * tanhf_(acc[1][mi][ni][1] + bu.y);
            creg[mi][ni][2] = sigf(acc[0][mi][ni][2] + bi.x) * tanhf_(acc[1][mi][ni][2] + bu.x);
            creg[mi][ni][3] = sigf(acc[0][mi][ni][3] + bi.y) * tanhf_(acc[1][mi][ni][3] + bu.y);
        }

    // ---- pass 1: f_l & f_r together ----
    run_pass<2, 8, 4>(g_Bpack + 65536, smem, sbase, tid, wm, wq, lane, acc, false);
    #pragma unroll
    for (int mi = 0; mi < 4; mi++) {
        int row0 = wm * 64 + mi * 16 + g;
        int ml0 = mapl_s[row0], ml1 = mapl_s[row0 + 8];
        int mr0 = mapr_s[row0], mr1 = mapr_s[row0 + 8];
        const float* cl0 = ((ml0 < 0) ? c_buf : c_bot) + (size_t)(uint32_t)(ml0 & 0x7fffffff) * DDIM;
        const float* cl1 = ((ml1 < 0) ? c_buf : c_bot) + (size_t)(uint32_t)(ml1 & 0x7fffffff) * DDIM;
        const float* cr0 = ((mr0 < 0) ? c_buf : c_bot) + (size_t)(uint32_t)(mr0 & 0x7fffffff) * DDIM;
        const float* cr1 = ((mr1 < 0) ? c_buf : c_bot) + (size_t)(uint32_t)(mr1 & 0x7fffffff) * DDIM;
        #pragma unroll
        for (int ni = 0; ni < 4; ni++) {
            int colg = wq * 32 + ni * 8 + tig * 2;
            float2 bl = *(const float2*)(bias_s + 384 + colg);   // f_l
            float2 br = *(const float2*)(bias_s + 512 + colg);   // f_r
            float2 vl0 = *(const float2*)(cl0 + colg);
            float2 vl1 = *(const float2*)(cl1 + colg);
            float2 vr0 = *(const float2*)(cr0 + colg);
            float2 vr1 = *(const float2*)(cr1 + colg);
            creg[mi][ni][0] = fmaf(sigf(acc[0][mi][ni][0] + bl.x), vl0.x, creg[mi][ni][0]);
            creg[mi][ni][1] = fmaf(sigf(acc[0][mi][ni][1] + bl.y), vl0.y, creg[mi][ni][1]);
            creg[mi][ni][2] = fmaf(sigf(acc[0][mi][ni][2] + bl.x), vl1.x, creg[mi][ni][2]);
            creg[mi][ni][3] = fmaf(sigf(acc[0][mi][ni][3] + bl.y), vl1.y, creg[mi][ni][3]);
            creg[mi][ni][0] = fmaf(sigf(acc[1][mi][ni][0] + br.x), vr0.x, creg[mi][ni][0]);
            creg[mi][ni][1] = fmaf(sigf(acc[1][mi][ni][1] + br.y), vr0.y, creg[mi][ni][1]);
            creg[mi][ni][2] = fmaf(sigf(acc[1][mi][ni][2] + br.x), vr1.x, creg[mi][ni][2]);
            creg[mi][ni][3] = fmaf(sigf(acc[1][mi][ni][3] + br.y), vr1.y, creg[mi][ni][3]);
        }
    }

    // ---- pass 2: o -> finalize h, c ----
    run_pass<1, 4, 8>(g_Bpack + 131072, smem, sbase, tid, wm, wq, lane, acc, false);
    #pragma unroll
    for (int mi = 0; mi < 4; mi++) {
        int row0 = wm * 64 + mi * 16 + g;
        size_t m0 = (size_t)(blk * 128 + row0);
        size_t m1 = m0 + 8;
        #pragma unroll
        for (int ni = 0; ni < 4; ni++) {
            int colg = wq * 32 + ni * 8 + tig * 2;
            float2 bo = *(const float2*)(bias_s + 128 + colg);   // o: cols 128..255
            float2 h0, h1, c0, c1;
            c0.x = creg[mi][ni][0]; h0.x = sigf(acc[0][mi][ni][0] + bo.x) * tanhf_(c0.x);
            c0.y = creg[mi][ni][1]; h0.y = sigf(acc[0][mi][ni][1] + bo.y) * tanhf_(c0.y);
            c1.x = creg[mi][ni][2]; h1.x = sigf(acc[0][mi][ni][2] + bo.x) * tanhf_(c1.x);
            c1.y = creg[mi][ni][3]; h1.y = sigf(acc[0][mi][ni][3] + bo.y) * tanhf_(c1.y);
            *(float2*)(out + m0 * DDIM + colg) = h0;
            *(float2*)(out + m1 * DDIM + colg) = h1;
            *(float2*)(out + (size_t)MROWS * DDIM + m0 * DDIM + colg) = c0;
            *(float2*)(out + (size_t)MROWS * DDIM + m1 * DDIM + colg) = c1;
        }
    }
}

// ---------------- launch ----------------
extern "C" void kernel_launch(void* const* d_in, const int* in_sizes, int n_in,
                              void* d_out, int out_size) {
    const float* h_bot = (const float*)d_in[0];
    const float* c_bot = (const float*)d_in[1];
    const float* h_buf = (const float*)d_in[2];
    const float* c_buf = (const float*)d_in[3];
    const float* W     = (const float*)d_in[4];
    const float* b     = (const float*)d_in[5];
    const int* bf0 = (const int*)d_in[6];
    const int* bt0 = (const int*)d_in[7];
    const int* pf0 = (const int*)d_in[8];
    const int* pt0 = (const int*)d_in[9];
    const int* bf1 = (const int*)d_in[10];
    const int* bt1 = (const int*)d_in[11];
    const int* pf1 = (const int*)d_in[12];
    const int* pt1 = (const int*)d_in[13];
    float* out = (float*)d_out;

    cudaFuncSetAttribute(treelstm_main, cudaFuncAttributeMaxDynamicSharedMemorySize, SMEM_TOTAL);

    build_rowmap<<<(KHALF + 255) / 256, 256>>>(bf0, bt0, pf0, pt0, bf1, bt1, pf1, pt1);
    pack_w<<<(256 * 640 + 255) / 256, 256>>>(W);
    treelstm_main<<<MROWS / 128, 256, SMEM_TOTAL>>>(h_bot, c_bot, h_buf, c_buf, b, out);
}

// round 6
// speedup vs baseline: 1.4972x; 1.1191x over previous
#include <cuda_runtime.h>
#include <cstdint>

#define DDIM   128
#define MROWS  131072
#define KHALF  (MROWS/2)

// ---------------- device scratch ----------------
__device__ int      g_rowmap_l[MROWS];
__device__ int      g_rowmap_r[MROWS];
// pass-major pre-swizzled tf32 B fragments (16KB chunks for passes 0/1, 16KB for pass2):
//  pass0 {i,u}:    words [0,      65536)  16 chunks (K=16, 2 gate slots of 2048 words)
//  pass1 {fl,fr}:  words [65536, 131072)  16 chunks (K=16, 2 gate slots)
//  pass2 {o}:      words [131072,163840)   8 chunks (K=32, 1 slot of 4096 words)
__device__ uint32_t g_Bpack[163840];

// ---------------- helpers ----------------
__device__ __forceinline__ uint32_t smem_u32(const void* p) {
    uint32_t a;
    asm("{ .reg .u64 t; cvta.to.shared.u64 t, %1; cvt.u32.u64 %0, t; }" : "=r"(a) : "l"(p));
    return a;
}
__device__ __forceinline__ uint32_t f2tf32(float f) {
    uint32_t r; asm("cvt.rna.tf32.f32 %0, %1;" : "=r"(r) : "f"(f)); return r;
}
__device__ __forceinline__ float ex2f(float x) {
    float y; asm("ex2.approx.f32 %0, %1;" : "=f"(y) : "f"(x)); return y;
}
__device__ __forceinline__ float rcpf(float x) {
    float y; asm("rcp.approx.f32 %0, %1;" : "=f"(y) : "f"(x)); return y;
}
__device__ __forceinline__ float sigf(float x) {
    return rcpf(1.0f + ex2f(-1.4426950408889634f * x));
}
__device__ __forceinline__ float tanhf_(float x) {
    return fmaf(2.0f, rcpf(1.0f + ex2f(-2.8853900817779268f * x)), -1.0f);
}
__device__ __forceinline__ void mma_tf32(float* d, const uint32_t* a, const uint32_t* b) {
    asm volatile(
        "mma.sync.aligned.m16n8k8.row.col.f32.tf32.tf32.f32 "
        "{%0,%1,%2,%3}, {%4,%5,%6,%7}, {%8,%9}, {%0,%1,%2,%3};"
        : "+f"(d[0]), "+f"(d[1]), "+f"(d[2]), "+f"(d[3])
        : "r"(a[0]), "r"(a[1]), "r"(a[2]), "r"(a[3]), "r"(b[0]), "r"(b[1]));
}
__device__ __forceinline__ void cpa16(uint32_t dst, const uint32_t* src) {
    asm volatile("cp.async.cg.shared.global [%0], [%1], 16;" :: "r"(dst), "l"(src));
}
__device__ __forceinline__ void cp_commit() {
    asm volatile("cp.async.commit_group;" ::: "memory");
}

// ---------------- SMEM layout (100 KB -> 2 CTAs/SM) ----------------
#define SMEM_BIAS  0          // 640 floats = 2560 B
#define SMEM_MAPL  2560       // 64 ints
#define SMEM_MAPR  2816       // 64 ints
#define SMEM_A     4096       // 64x256 tf32 fragment-packed = 65536 B
#define SMEM_B0    69632      // 16 KB
#define SMEM_B1    86016      // 16 KB
#define SMEM_TOTAL 102400

// A pack byte offset (relative to SMEM_A) for element (r,k), r in [0,64)
__device__ __forceinline__ uint32_t a_off(int r, int k) {
    int mt = r >> 4, kk = k >> 3;
    int lane = ((r & 7) << 2) | (k & 3);
    int slot = ((r >> 3) & 1) | (((k >> 2) & 1) << 1);
    return (uint32_t)((((mt << 5) + kk) << 5) + (lane ^ (kk & 7))) * 16u + (uint32_t)slot * 4u;
}

// ---------------- prep kernels ----------------
__global__ void build_rowmap(const int* __restrict__ bf0, const int* __restrict__ bt0,
                             const int* __restrict__ pf0, const int* __restrict__ pt0,
                             const int* __restrict__ bf1, const int* __restrict__ bt1,
                             const int* __restrict__ pf1, const int* __restrict__ pt1) {
    int i = blockIdx.x * blockDim.x + threadIdx.x;
    if (i >= KHALF) return;
    g_rowmap_l[bt0[i]] = bf0[i];
    g_rowmap_l[pt0[i]] = (int)((uint32_t)pf0[i] | 0x80000000u);
    g_rowmap_r[bt1[i]] = bf1[i];
    g_rowmap_r[pt1[i]] = (int)((uint32_t)pf1[i] | 0x80000000u);
}

// W [256,640] row-major -> pass-major fragment layout (see g_Bpack comment)
// column blocks of 128: 0:i 1:o 2:u 3:f_l 4:f_r
__global__ void pack_w(const float* __restrict__ W) {
    int idx = blockIdx.x * blockDim.x + threadIdx.x;
    if (idx >= 256 * 640) return;
    int k = idx / 640, col = idx % 640;
    int gate = col >> 7, n = col & 127;
    int pass, slot;
    if      (gate == 0) { pass = 0; slot = 0; }   // i
    else if (gate == 2) { pass = 0; slot = 1; }   // u
    else if (gate == 3) { pass = 1; slot = 0; }   // f_l
    else if (gate == 4) { pass = 1; slot = 1; }   // f_r
    else                { pass = 2; slot = 0; }   // o
    int nt = n >> 3, nl = n & 7;
    int kl = k & 7;
    int lane = (nl << 2) | (kl & 3);
    int ws = (kl >> 2) & 1;
    int off;
    if (pass < 2) {  // K-chunk 16, 2 slots of 2048 words
        int chunk = k >> 4, kk = (k >> 3) & 1;
        off = pass * 65536 + chunk * 4096 + slot * 2048
            + ((kk * 8 + (nt >> 1)) * 32 + lane) * 4 + (nt & 1) * 2 + ws;
    } else {         // K-chunk 32, 1 slot of 4096 words
        int chunk = k >> 5, kk = (k >> 3) & 3;
        off = 131072 + chunk * 4096
            + ((kk * 8 + (nt >> 1)) * 32 + lane) * 4 + (nt & 1) * 2 + ws;
    }
    g_Bpack[off] = f2tf32(W[idx]);
}

// ---------------- pipelined MMA pass ----------------
// one 16 KB chunk = 4096 words = 1024 x 16B units
__device__ __forceinline__ void issue_chunk16(uint32_t sdst, const uint32_t* src, int tid) {
    #pragma unroll
    for (int i = 0; i < 4; i++) {
        int unit = i * 256 + tid;
        cpa16(sdst + (uint32_t)unit * 16u, src + unit * 4);
    }
    cp_commit();
}

// NS gate slots per chunk, NCH chunks (even), KS k8-steps per chunk (NS*KS == 4)
// nextW: first chunk of the following pass (prefetched during last chunk), or null
template<int NS, int NCH, int KS>
__device__ __forceinline__ void run_pass(const uint32_t* __restrict__ gW,
                                         const uint32_t* __restrict__ nextW,
                                         char* smem, uint32_t sbase,
                                         int tid, int wm, int wq, int lane,
                                         float acc[][2][4][4]) {
    #pragma unroll
    for (int s = 0; s < NS; s++)
        #pragma unroll
        for (int mi = 0; mi < 2; mi++)
            #pragma unroll
            for (int ni = 0; ni < 4; ni++)
                #pragma unroll
                for (int c = 0; c < 4; c++) acc[s][mi][ni][c] = 0.0f;

    #pragma unroll 1
    for (int c = 0; c < NCH; c++) {
        if (c < NCH - 1) {
            issue_chunk16(sbase + ((c & 1) ? SMEM_B0 : SMEM_B1), gW + (c + 1) * 4096, tid);
            asm volatile("cp.async.wait_group 1;" ::: "memory");
        } else if (nextW) {
            // prefetch next pass chunk0 into the free buffer (lands in B0: NCH even)
            issue_chunk16(sbase + ((c & 1) ? SMEM_B0 : SMEM_B1), nextW, tid);
            asm volatile("cp.async.wait_group 1;" ::: "memory");
        } else {
            asm volatile("cp.async.wait_group 0;" ::: "memory");
        }
        __syncthreads();
        const char* bb = smem + ((c & 1) ? SMEM_B1 : SMEM_B0);

        #pragma unroll
        for (int kk = 0; kk < KS; kk++) {
            const int kkg = c * KS + kk;
            uint32_t a[2][4];
            #pragma unroll
            for (int mi = 0; mi < 2; mi++) {
                uint4 v = *(const uint4*)(smem + SMEM_A +
                    (uint32_t)((((wm * 2 + mi) * 32 + kkg) * 32) + (lane ^ (kkg & 7))) * 16u);
                a[mi][0] = v.x; a[mi][1] = v.y; a[mi][2] = v.z; a[mi][3] = v.w;
            }
            uint32_t b[NS][4][2];
            #pragma unroll
            for (int s = 0; s < NS; s++)
                #pragma unroll
                for (int np2 = 0; np2 < 2; np2++) {
                    uint4 v = *(const uint4*)(bb + s * 8192 +
                        (uint32_t)(((kk * 8 + wq * 2 + np2) * 32) + lane) * 16u);
                    b[s][np2 * 2][0]     = v.x; b[s][np2 * 2][1]     = v.y;
                    b[s][np2 * 2 + 1][0] = v.z; b[s][np2 * 2 + 1][1] = v.w;
                }
            #pragma unroll
            for (int s = 0; s < NS; s++)
                #pragma unroll
                for (int mi = 0; mi < 2; mi++)
                    #pragma unroll
                    for (int ni = 0; ni < 4; ni++)
                        mma_tf32(acc[s][mi][ni], a[mi], b[s][ni]);
        }
        __syncthreads();
    }
}

// ---------------- main fused kernel ----------------
__global__ void __launch_bounds__(256, 2) treelstm_main(
    const float* __restrict__ h_bot, const float* __restrict__ c_bot,
    const float* __restrict__ h_buf, const float* __restrict__ c_buf,
    const float* __restrict__ bias,  float* __restrict__ out) {
    extern __shared__ char smem[];
    const uint32_t sbase = smem_u32(smem);
    float* bias_s = (float*)(smem + SMEM_BIAS);
    int*   mapl_s = (int*)(smem + SMEM_MAPL);
    int*   mapr_s = (int*)(smem + SMEM_MAPR);

    const int tid = threadIdx.x, wid = tid >> 5, lane = tid & 31;
    const int g = lane >> 2, tig = lane & 3;
    const int wm = wid & 1, wq = wid >> 1;
    const int blk = blockIdx.x;

    // preload pass0 chunk0 so its latency hides under the A gather
    issue_chunk16(sbase + SMEM_B0, g_Bpack, tid);

    for (int t = tid; t < 640; t += 256) bias_s[t] = bias[t];
    if (tid < 64) {
        mapl_s[tid] = g_rowmap_l[blk * 64 + tid];
        mapr_s[tid] = g_rowmap_r[blk * 64 + tid];
    }

    // ---- gather X = [h_l | h_r] into fragment-packed A (tf32) ----
    // 64 rows x 2 sources = 128 warp-jobs
    for (int j = wid; j < 128; j += 8) {
        int src = j & 1, r = j >> 1;
        int m = blk * 64 + r;
        int map = src ? g_rowmap_r[m] : g_rowmap_l[m];
        const float* sp = ((map < 0) ? h_buf : h_bot) + (size_t)(uint32_t)(map & 0x7fffffff) * DDIM;
        float4 v = ((const float4*)sp)[lane];
        int k0 = src * 128 + lane * 4;
        char* ab = smem + SMEM_A;
        *(uint32_t*)(ab + a_off(r, k0 + 0)) = f2tf32(v.x);
        *(uint32_t*)(ab + a_off(r, k0 + 1)) = f2tf32(v.y);
        *(uint32_t*)(ab + a_off(r, k0 + 2)) = f2tf32(v.z);
        *(uint32_t*)(ab + a_off(r, k0 + 3)) = f2tf32(v.w);
    }
    // first __syncthreads inside run_pass orders gather/maps before use

    float acc[2][2][4][4];
    float creg[2][4][4];

    // ---- pass 0: gates i & u ----
    run_pass<2, 16, 2>(g_Bpack, g_Bpack + 65536, smem, sbase, tid, wm, wq, lane, acc);
    #pragma unroll
    for (int mi = 0; mi < 2; mi++)
        #pragma unroll
        for (int ni = 0; ni < 4; ni++) {
            int colg = wq * 32 + ni * 8 + tig * 2;
            float2 bi = *(const float2*)(bias_s + colg);         // i: cols 0..127
            float2 bu = *(const float2*)(bias_s + 256 + colg);   // u: cols 256..383
            creg[mi][ni][0] = sigf(acc[0][mi][ni][0] + bi.x) * tanhf_(acc[1][mi][ni][0] + bu.x);
            creg[mi][ni][1] = sigf(acc[0][mi][ni][1] + bi.y) * tanhf_(acc[1][mi][ni][1] + bu.y);
            creg[mi][ni][2] = sigf(acc[0][mi][ni][2] + bi.x) * tanhf_(acc[1][mi][ni][2] + bu.x);
            creg[mi][ni][3] = sigf(acc[0][mi][ni][3] + bi.y) * tanhf_(acc[1][mi][ni][3] + bu.y);
        }

    // ---- pass 1: f_l & f_r together ----
    run_pass<2, 16, 2>(g_Bpack + 65536, g_Bpack + 131072, smem, sbase, tid, wm, wq, lane, acc);
    #pragma unroll
    for (int mi = 0; mi < 2; mi++) {
        int row0 = wm * 32 + mi * 16 + g;
        int ml0 = mapl_s[row0], ml1 = mapl_s[row0 + 8];
        int mr0 = mapr_s[row0], mr1 = mapr_s[row0 + 8];
        const float* cl0 = ((ml0 < 0) ? c_buf : c_bot) + (size_t)(uint32_t)(ml0 & 0x7fffffff) * DDIM;
        const float* cl1 = ((ml1 < 0) ? c_buf : c_bot) + (size_t)(uint32_t)(ml1 & 0x7fffffff) * DDIM;
        const float* cr0 = ((mr0 < 0) ? c_buf : c_bot) + (size_t)(uint32_t)(mr0 & 0x7fffffff) * DDIM;
        const float* cr1 = ((mr1 < 0) ? c_buf : c_bot) + (size_t)(uint32_t)(mr1 & 0x7fffffff) * DDIM;
        #pragma unroll
        for (int ni = 0; ni < 4; ni++) {
            int colg = wq * 32 + ni * 8 + tig * 2;
            float2 bl = *(const float2*)(bias_s + 384 + colg);   // f_l
            float2 br = *(const float2*)(bias_s + 512 + colg);   // f_r
            float2 vl0 = *(const float2*)(cl0 + colg);
            float2 vl1 = *(const float2*)(cl1 + colg);
            float2 vr0 = *(const float2*)(cr0 + colg);
            float2 vr1 = *(const float2*)(cr1 + colg);
            creg[mi][ni][0] = fmaf(sigf(acc[0][mi][ni][0] + bl.x), vl0.x, creg[mi][ni][0]);
            creg[mi][ni][1] = fmaf(sigf(acc[0][mi][ni][1] + bl.y), vl0.y, creg[mi][ni][1]);
            creg[mi][ni][2] = fmaf(sigf(acc[0][mi][ni][2] + bl.x), vl1.x, creg[mi][ni][2]);
            creg[mi][ni][3] = fmaf(sigf(acc[0][mi][ni][3] + bl.y), vl1.y, creg[mi][ni][3]);
            creg[mi][ni][0] = fmaf(sigf(acc[1][mi][ni][0] + br.x), vr0.x, creg[mi][ni][0]);
            creg[mi][ni][1] = fmaf(sigf(acc[1][mi][ni][1] + br.y), vr0.y, creg[mi][ni][1]);
            creg[mi][ni][2] = fmaf(sigf(acc[1][mi][ni][2] + br.x), vr1.x, creg[mi][ni][2]);
            creg[mi][ni][3] = fmaf(sigf(acc[1][mi][ni][3] + br.y), vr1.y, creg[mi][ni][3]);
        }
    }

    // ---- pass 2: o -> finalize h, c ----
    run_pass<1, 8, 4>(g_Bpack + 131072, nullptr, smem, sbase, tid, wm, wq, lane, acc);
    #pragma unroll
    for (int mi = 0; mi < 2; mi++) {
        int row0 = wm * 32 + mi * 16 + g;
        size_t m0 = (size_t)(blk * 64 + row0);
        size_t m1 = m0 + 8;
        #pragma unroll
        for (int ni = 0; ni < 4; ni++) {
            int colg = wq * 32 + ni * 8 + tig * 2;
            float2 bo = *(const float2*)(bias_s + 128 + colg);   // o: cols 128..255
            float2 h0, h1, c0, c1;
            c0.x = creg[mi][ni][0]; h0.x = sigf(acc[0][mi][ni][0] + bo.x) * tanhf_(c0.x);
            c0.y = creg[mi][ni][1]; h0.y = sigf(acc[0][mi][ni][1] + bo.y) * tanhf_(c0.y);
            c1.x = creg[mi][ni][2]; h1.x = sigf(acc[0][mi][ni][2] + bo.x) * tanhf_(c1.x);
            c1.y = creg[mi][ni][3]; h1.y = sigf(acc[0][mi][ni][3] + bo.y) * tanhf_(c1.y);
            *(float2*)(out + m0 * DDIM + colg) = h0;
            *(float2*)(out + m1 * DDIM + colg) = h1;
            *(float2*)(out + (size_t)MROWS * DDIM + m0 * DDIM + colg) = c0;
            *(float2*)(out + (size_t)MROWS * DDIM + m1 * DDIM + colg) = c1;
        }
    }
}

// ---------------- launch ----------------
extern "C" void kernel_launch(void* const* d_in, const int* in_sizes, int n_in,
                              void* d_out, int out_size) {
    const float* h_bot = (const float*)d_in[0];
    const float* c_bot = (const float*)d_in[1];
    const float* h_buf = (const float*)d_in[2];
    const float* c_buf = (const float*)d_in[3];
    const float* W     = (const float*)d_in[4];
    const float* b     = (const float*)d_in[5];
    const int* bf0 = (const int*)d_in[6];
    const int* bt0 = (const int*)d_in[7];
    const int* pf0 = (const int*)d_in[8];
    const int* pt0 = (const int*)d_in[9];
    const int* bf1 = (const int*)d_in[10];
    const int* bt1 = (const int*)d_in[11];
    const int* pf1 = (const int*)d_in[12];
    const int* pt1 = (const int*)d_in[13];
    float* out = (float*)d_out;

    cudaFuncSetAttribute(treelstm_main, cudaFuncAttributeMaxDynamicSharedMemorySize, SMEM_TOTAL);

    build_rowmap<<<(KHALF + 255) / 256, 256>>>(bf0, bt0, pf0, pt0, bf1, bt1, pf1, pt1);
    pack_w<<<(256 * 640 + 255) / 256, 256>>>(W);
    treelstm_main<<<MROWS / 64, 256, SMEM_TOTAL>>>(h_bot, c_bot, h_buf, c_buf, b, out);
}

// round 7
// speedup vs baseline: 1.5462x; 1.0327x over previous
#include <cuda_runtime.h>
#include <cstdint>

#define DDIM   128
#define MROWS  131072
#define KHALF  (MROWS/2)

// ---------------- device scratch ----------------
__device__ int      g_rowmap_l[MROWS];
__device__ int      g_rowmap_r[MROWS];
// pass-major pre-swizzled tf32 B fragments:
//  pass0 {i,u}:    words [0,      65536)  16 chunks (K=16, 2 gate slots of 2048 words)
//  pass1 {fl,fr}:  words [65536, 131072)  16 chunks (K=16, 2 gate slots)
//  pass2 {o}:      words [131072,163840)   8 chunks (K=32, 1 slot of 4096 words)
__device__ uint32_t g_Bpack[163840];

// ---------------- helpers ----------------
__device__ __forceinline__ uint32_t smem_u32(const void* p) {
    uint32_t a;
    asm("{ .reg .u64 t; cvta.to.shared.u64 t, %1; cvt.u32.u64 %0, t; }" : "=r"(a) : "l"(p));
    return a;
}
__device__ __forceinline__ uint32_t f2tf32(float f) {
    uint32_t r; asm("cvt.rna.tf32.f32 %0, %1;" : "=r"(r) : "f"(f)); return r;
}
__device__ __forceinline__ float ex2f(float x) {
    float y; asm("ex2.approx.f32 %0, %1;" : "=f"(y) : "f"(x)); return y;
}
__device__ __forceinline__ float rcpf(float x) {
    float y; asm("rcp.approx.f32 %0, %1;" : "=f"(y) : "f"(x)); return y;
}
__device__ __forceinline__ float sigf(float x) {
    return rcpf(1.0f + ex2f(-1.4426950408889634f * x));
}
__device__ __forceinline__ float tanhf_(float x) {
    return fmaf(2.0f, rcpf(1.0f + ex2f(-2.8853900817779268f * x)), -1.0f);
}
__device__ __forceinline__ void mma_tf32(float* d, const uint32_t* a, const uint32_t* b) {
    asm volatile(
        "mma.sync.aligned.m16n8k8.row.col.f32.tf32.tf32.f32 "
        "{%0,%1,%2,%3}, {%4,%5,%6,%7}, {%8,%9}, {%0,%1,%2,%3};"
        : "+f"(d[0]), "+f"(d[1]), "+f"(d[2]), "+f"(d[3])
        : "r"(a[0]), "r"(a[1]), "r"(a[2]), "r"(a[3]), "r"(b[0]), "r"(b[1]));
}
__device__ __forceinline__ void cpa16(uint32_t dst, const uint32_t* src) {
    asm volatile("cp.async.cg.shared.global [%0], [%1], 16;" :: "r"(dst), "l"(src));
}
__device__ __forceinline__ void cp_commit() {
    asm volatile("cp.async.commit_group;" ::: "memory");
}
__device__ __forceinline__ void pf_l2(const void* p) {
    asm volatile("prefetch.global.L2 [%0];" :: "l"(p));
}

// ---------------- SMEM layout (100 KB -> 2 CTAs/SM) ----------------
#define SMEM_BIAS  0          // 640 floats = 2560 B
#define SMEM_MAPL  2560       // 64 ints
#define SMEM_MAPR  2816       // 64 ints
#define SMEM_A     4096       // 64x256 tf32 fragment-packed = 65536 B
#define SMEM_B0    69632      // 16 KB
#define SMEM_B1    86016      // 16 KB
#define SMEM_TOTAL 102400

// A pack byte offset (relative to SMEM_A) for element (r,k), r in [0,64)
__device__ __forceinline__ uint32_t a_off(int r, int k) {
    int mt = r >> 4, kk = k >> 3;
    int lane = ((r & 7) << 2) | (k & 3);
    int slot = ((r >> 3) & 1) | (((k >> 2) & 1) << 1);
    return (uint32_t)((((mt << 5) + kk) << 5) + (lane ^ (kk & 7))) * 16u + (uint32_t)slot * 4u;
}

// ---------------- single merged prep kernel (keeps launch count at 2) ----------------
// grid 640 x 256: idx < 163840 does pack_w, idx < KHALF also does rowmap
__global__ void prep_all(const float* __restrict__ W,
                         const int* __restrict__ bf0, const int* __restrict__ bt0,
                         const int* __restrict__ pf0, const int* __restrict__ pt0,
                         const int* __restrict__ bf1, const int* __restrict__ bt1,
                         const int* __restrict__ pf1, const int* __restrict__ pt1) {
    int idx = blockIdx.x * blockDim.x + threadIdx.x;
    if (idx < KHALF) {
        g_rowmap_l[bt0[idx]] = bf0[idx];
        g_rowmap_l[pt0[idx]] = (int)((uint32_t)pf0[idx] | 0x80000000u);
        g_rowmap_r[bt1[idx]] = bf1[idx];
        g_rowmap_r[pt1[idx]] = (int)((uint32_t)pf1[idx] | 0x80000000u);
    }
    if (idx < 256 * 640) {
        int k = idx / 640, col = idx % 640;
        int gate = col >> 7, n = col & 127;     // gates: 0:i 1:o 2:u 3:f_l 4:f_r
        int pass, slot;
        if      (gate == 0) { pass = 0; slot = 0; }
        else if (gate == 2) { pass = 0; slot = 1; }
        else if (gate == 3) { pass = 1; slot = 0; }
        else if (gate == 4) { pass = 1; slot = 1; }
        else                { pass = 2; slot = 0; }
        int nt = n >> 3, nl = n & 7;
        int kl = k & 7;
        int lane = (nl << 2) | (kl & 3);
        int ws = (kl >> 2) & 1;
        int off;
        if (pass < 2) {  // K-chunk 16, 2 slots of 2048 words
            int chunk = k >> 4, kk = (k >> 3) & 1;
            off = pass * 65536 + chunk * 4096 + slot * 2048
                + ((kk * 8 + (nt >> 1)) * 32 + lane) * 4 + (nt & 1) * 2 + ws;
        } else {         // K-chunk 32, 1 slot of 4096 words
            int chunk = k >> 5, kk = (k >> 3) & 3;
            off = 131072 + chunk * 4096
                + ((kk * 8 + (nt >> 1)) * 32 + lane) * 4 + (nt & 1) * 2 + ws;
        }
        g_Bpack[off] = f2tf32(W[idx]);
    }
}

// ---------------- pipelined MMA pass ----------------
// one 16 KB chunk = 4096 words = 1024 x 16B units
__device__ __forceinline__ void issue_chunk16(uint32_t sdst, const uint32_t* src, int tid) {
    #pragma unroll
    for (int i = 0; i < 4; i++) {
        int unit = i * 256 + tid;
        cpa16(sdst + (uint32_t)unit * 16u, src + unit * 4);
    }
    cp_commit();
}

// NS gate slots per chunk, NCH chunks (even), KS k8-steps per chunk (NS*KS == 4)
template<int NS, int NCH, int KS>
__device__ __forceinline__ void run_pass(const uint32_t* __restrict__ gW,
                                         const uint32_t* __restrict__ nextW,
                                         char* smem, uint32_t sbase,
                                         int tid, int wm, int wq, int lane,
                                         float acc[][2][4][4]) {
    #pragma unroll
    for (int s = 0; s < NS; s++)
        #pragma unroll
        for (int mi = 0; mi < 2; mi++)
            #pragma unroll
            for (int ni = 0; ni < 4; ni++)
                #pragma unroll
                for (int c = 0; c < 4; c++) acc[s][mi][ni][c] = 0.0f;

    #pragma unroll 1
    for (int c = 0; c < NCH; c++) {
        if (c < NCH - 1) {
            issue_chunk16(sbase + ((c & 1) ? SMEM_B0 : SMEM_B1), gW + (c + 1) * 4096, tid);
            asm volatile("cp.async.wait_group 1;" ::: "memory");
        } else if (nextW) {
            issue_chunk16(sbase + ((c & 1) ? SMEM_B0 : SMEM_B1), nextW, tid);
            asm volatile("cp.async.wait_group 1;" ::: "memory");
        } else {
            asm volatile("cp.async.wait_group 0;" ::: "memory");
        }
        __syncthreads();
        const char* bb = smem + ((c & 1) ? SMEM_B1 : SMEM_B0);

        #pragma unroll
        for (int kk = 0; kk < KS; kk++) {
            const int kkg = c * KS + kk;
            uint32_t a[2][4];
            #pragma unroll
            for (int mi = 0; mi < 2; mi++) {
                uint4 v = *(const uint4*)(smem + SMEM_A +
                    (uint32_t)((((wm * 2 + mi) * 32 + kkg) * 32) + (lane ^ (kkg & 7))) * 16u);
                a[mi][0] = v.x; a[mi][1] = v.y; a[mi][2] = v.z; a[mi][3] = v.w;
            }
            uint32_t b[NS][4][2];
            #pragma unroll
            for (int s = 0; s < NS; s++)
                #pragma unroll
                for (int np2 = 0; np2 < 2; np2++) {
                    uint4 v = *(const uint4*)(bb + s * 8192 +
                        (uint32_t)(((kk * 8 + wq * 2 + np2) * 32) + lane) * 16u);
                    b[s][np2 * 2][0]     = v.x; b[s][np2 * 2][1]     = v.y;
                    b[s][np2 * 2 + 1][0] = v.z; b[s][np2 * 2 + 1][1] = v.w;
                }
            #pragma unroll
            for (int s = 0; s < NS; s++)
                #pragma unroll
                for (int mi = 0; mi < 2; mi++)
                    #pragma unroll
                    for (int ni = 0; ni < 4; ni++)
                        mma_tf32(acc[s][mi][ni], a[mi], b[s][ni]);
        }
        __syncthreads();
    }
}

// ---------------- main fused kernel ----------------
__global__ void __launch_bounds__(256, 2) treelstm_main(
    const float* __restrict__ h_bot, const float* __restrict__ c_bot,
    const float* __restrict__ h_buf, const float* __restrict__ c_buf,
    const float* __restrict__ bias,  float* __restrict__ out) {
    extern __shared__ char smem[];
    const uint32_t sbase = smem_u32(smem);
    float* bias_s = (float*)(smem + SMEM_BIAS);
    int*   mapl_s = (int*)(smem + SMEM_MAPL);
    int*   mapr_s = (int*)(smem + SMEM_MAPR);

    const int tid = threadIdx.x, wid = tid >> 5, lane = tid & 31;
    const int g = lane >> 2, tig = lane & 3;
    const int wm = wid & 1, wq = wid >> 1;
    const int blk = blockIdx.x;

    // preload pass0 chunk0 so its latency hides under the A gather
    issue_chunk16(sbase + SMEM_B0, g_Bpack, tid);

    for (int t = tid; t < 640; t += 256) bias_s[t] = bias[t];
    if (tid < 64) {
        mapl_s[tid] = g_rowmap_l[blk * 64 + tid];
        mapr_s[tid] = g_rowmap_r[blk * 64 + tid];
    }

    // ---- gather X = [h_l | h_r] into fragment-packed A (tf32) ----
    for (int j = wid; j < 128; j += 8) {
        int src = j & 1, r = j >> 1;
        int m = blk * 64 + r;
        int map = src ? g_rowmap_r[m] : g_rowmap_l[m];
        const float* sp = ((map < 0) ? h_buf : h_bot) + (size_t)(uint32_t)(map & 0x7fffffff) * DDIM;
        float4 v = ((const float4*)sp)[lane];
        int k0 = src * 128 + lane * 4;
        char* ab = smem + SMEM_A;
        *(uint32_t*)(ab + a_off(r, k0 + 0)) = f2tf32(v.x);
        *(uint32_t*)(ab + a_off(r, k0 + 1)) = f2tf32(v.y);
        *(uint32_t*)(ab + a_off(r, k0 + 2)) = f2tf32(v.z);
        *(uint32_t*)(ab + a_off(r, k0 + 3)) = f2tf32(v.w);
    }

    float acc[2][2][4][4];
    float creg[2][4][4];

    // ---- pass 0: gates i & u ----
    run_pass<2, 16, 2>(g_Bpack, g_Bpack + 65536, smem, sbase, tid, wm, wq, lane, acc);
    #pragma unroll
    for (int mi = 0; mi < 2; mi++)
        #pragma unroll
        for (int ni = 0; ni < 4; ni++) {
            int colg = wq * 32 + ni * 8 + tig * 2;
            float2 bi = *(const float2*)(bias_s + colg);         // i: cols 0..127
            float2 bu = *(const float2*)(bias_s + 256 + colg);   // u: cols 256..383
            creg[mi][ni][0] = sigf(acc[0][mi][ni][0] + bi.x) * tanhf_(acc[1][mi][ni][0] + bu.x);
            creg[mi][ni][1] = sigf(acc[0][mi][ni][1] + bi.y) * tanhf_(acc[1][mi][ni][1] + bu.y);
            creg[mi][ni][2] = sigf(acc[0][mi][ni][2] + bi.x) * tanhf_(acc[1][mi][ni][2] + bu.x);
            creg[mi][ni][3] = sigf(acc[0][mi][ni][3] + bi.y) * tanhf_(acc[1][mi][ni][3] + bu.y);
        }

    // ---- L2-prefetch the c_l/c_r rows this thread will gather after pass 1 ----
    {
        const int colb = wq * 32;   // this thread's 128B span within each row
        #pragma unroll
        for (int mi = 0; mi < 2; mi++) {
            int row0 = wm * 32 + mi * 16 + g;
            int ml0 = mapl_s[row0], ml1 = mapl_s[row0 + 8];
            int mr0 = mapr_s[row0], mr1 = mapr_s[row0 + 8];
            pf_l2(((ml0 < 0) ? c_buf : c_bot) + (size_t)(uint32_t)(ml0 & 0x7fffffff) * DDIM + colb);
            pf_l2(((ml1 < 0) ? c_buf : c_bot) + (size_t)(uint32_t)(ml1 & 0x7fffffff) * DDIM + colb);
            pf_l2(((mr0 < 0) ? c_buf : c_bot) + (size_t)(uint32_t)(mr0 & 0x7fffffff) * DDIM + colb);
            pf_l2(((mr1 < 0) ? c_buf : c_bot) + (size_t)(uint32_t)(mr1 & 0x7fffffff) * DDIM + colb);
        }
    }

    // ---- pass 1: f_l & f_r together ----
    run_pass<2, 16, 2>(g_Bpack + 65536, g_Bpack + 131072, smem, sbase, tid, wm, wq, lane, acc);
    #pragma unroll
    for (int mi = 0; mi < 2; mi++) {
        int row0 = wm * 32 + mi * 16 + g;
        int ml0 = mapl_s[row0], ml1 = mapl_s[row0 + 8];
        int mr0 = mapr_s[row0], mr1 = mapr_s[row0 + 8];
        const float* cl0 = ((ml0 < 0) ? c_buf : c_bot) + (size_t)(uint32_t)(ml0 & 0x7fffffff) * DDIM;
        const float* cl1 = ((ml1 < 0) ? c_buf : c_bot) + (size_t)(uint32_t)(ml1 & 0x7fffffff) * DDIM;
        const float* cr0 = ((mr0 < 0) ? c_buf : c_bot) + (size_t)(uint32_t)(mr0 & 0x7fffffff) * DDIM;
        const float* cr1 = ((mr1 < 0) ? c_buf : c_bot) + (size_t)(uint32_t)(mr1 & 0x7fffffff) * DDIM;
        #pragma unroll
        for (int ni = 0; ni < 4; ni++) {
            int colg = wq * 32 + ni * 8 + tig * 2;
            float2 bl = *(const float2*)(bias_s + 384 + colg);   // f_l
            float2 br = *(const float2*)(bias_s + 512 + colg);   // f_r
            float2 vl0 = *(const float2*)(cl0 + colg);
            float2 vl1 = *(const float2*)(cl1 + colg);
            float2 vr0 = *(const float2*)(cr0 + colg);
            float2 vr1 = *(const float2*)(cr1 + colg);
            creg[mi][ni][0] = fmaf(sigf(acc[0][mi][ni][0] + bl.x), vl0.x, creg[mi][ni][0]);
            creg[mi][ni][1] = fmaf(sigf(acc[0][mi][ni][1] + bl.y), vl0.y, creg[mi][ni][1]);
            creg[mi][ni][2] = fmaf(sigf(acc[0][mi][ni][2] + bl.x), vl1.x, creg[mi][ni][2]);
            creg[mi][ni][3] = fmaf(sigf(acc[0][mi][ni][3] + bl.y), vl1.y, creg[mi][ni][3]);
            creg[mi][ni][0] = fmaf(sigf(acc[1][mi][ni][0] + br.x), vr0.x, creg[mi][ni][0]);
            creg[mi][ni][1] = fmaf(sigf(acc[1][mi][ni][1] + br.y), vr0.y, creg[mi][ni][1]);
            creg[mi][ni][2] = fmaf(sigf(acc[1][mi][ni][2] + br.x), vr1.x, creg[mi][ni][2]);
            creg[mi][ni][3] = fmaf(sigf(acc[1][mi][ni][3] + br.y), vr1.y, creg[mi][ni][3]);
        }
    }

    // ---- pass 2: o -> finalize h, c ----
    run_pass<1, 8, 4>(g_Bpack + 131072, nullptr, smem, sbase, tid, wm, wq, lane, acc);
    #pragma unroll
    for (int mi = 0; mi < 2; mi++) {
        int row0 = wm * 32 + mi * 16 + g;
        size_t m0 = (size_t)(blk * 64 + row0);
        size_t m1 = m0 + 8;
        #pragma unroll
        for (int ni = 0; ni < 4; ni++) {
            int colg = wq * 32 + ni * 8 + tig * 2;
            float2 bo = *(const float2*)(bias_s + 128 + colg);   // o: cols 128..255
            float2 h0, h1, c0, c1;
            c0.x = creg[mi][ni][0]; h0.x = sigf(acc[0][mi][ni][0] + bo.x) * tanhf_(c0.x);
            c0.y = creg[mi][ni][1]; h0.y = sigf(acc[0][mi][ni][1] + bo.y) * tanhf_(c0.y);
            c1.x = creg[mi][ni][2]; h1.x = sigf(acc[0][mi][ni][2] + bo.x) * tanhf_(c1.x);
            c1.y = creg[mi][ni][3]; h1.y = sigf(acc[0][mi][ni][3] + bo.y) * tanhf_(c1.y);
            *(float2*)(out + m0 * DDIM + colg) = h0;
            *(float2*)(out + m1 * DDIM + colg) = h1;
            *(float2*)(out + (size_t)MROWS * DDIM + m0 * DDIM + colg) = c0;
            *(float2*)(out + (size_t)MROWS * DDIM + m1 * DDIM + colg) = c1;
        }
    }
}

// ---------------- launch ----------------
extern "C" void kernel_launch(void* const* d_in, const int* in_sizes, int n_in,
                              void* d_out, int out_size) {
    const float* h_bot = (const float*)d_in[0];
    const float* c_bot = (const float*)d_in[1];
    const float* h_buf = (const float*)d_in[2];
    const float* c_buf = (const float*)d_in[3];
    const float* W     = (const float*)d_in[4];
    const float* b     = (const float*)d_in[5];
    const int* bf0 = (const int*)d_in[6];
    const int* bt0 = (const int*)d_in[7];
    const int* pf0 = (const int*)d_in[8];
    const int* pt0 = (const int*)d_in[9];
    const int* bf1 = (const int*)d_in[10];
    const int* bt1 = (const int*)d_in[11];
    const int* pf1 = (const int*)d_in[12];
    const int* pt1 = (const int*)d_in[13];
    float* out = (float*)d_out;

    cudaFuncSetAttribute(treelstm_main, cudaFuncAttributeMaxDynamicSharedMemorySize, SMEM_TOTAL);

    prep_all<<<640, 256>>>(W, bf0, bt0, pf0, pt0, bf1, bt1, pf1, pt1);
    treelstm_main<<<MROWS / 64, 256, SMEM_TOTAL>>>(h_bot, c_bot, h_buf, c_buf, b, out);
}

// round 8
// speedup vs baseline: 1.5644x; 1.0117x over previous
#include <cuda_runtime.h>
#include <cstdint>

#define DDIM   128
#define MROWS  131072
#define KHALF  (MROWS/2)

// ---------------- device scratch ----------------
__device__ int      g_rowmap_l[MROWS];
__device__ int      g_rowmap_r[MROWS];
// pass-major pre-swizzled tf32 B fragments:
//  pass0 {i,u}:    words [0,      65536)  16 chunks (K=16, 2 gate slots of 2048 words)
//  pass1 {fl,fr}:  words [65536, 131072)  16 chunks (K=16, 2 gate slots)
//  pass2 {o}:      words [131072,163840)   8 chunks (K=32, 1 slot of 4096 words)
__device__ uint32_t g_Bpack[163840];

// ---------------- helpers ----------------
__device__ __forceinline__ uint32_t smem_u32(const void* p) {
    uint32_t a;
    asm("{ .reg .u64 t; cvta.to.shared.u64 t, %1; cvt.u32.u64 %0, t; }" : "=r"(a) : "l"(p));
    return a;
}
__device__ __forceinline__ uint32_t f2tf32(float f) {
    uint32_t r; asm("cvt.rna.tf32.f32 %0, %1;" : "=r"(r) : "f"(f)); return r;
}
__device__ __forceinline__ float ex2f(float x) {
    float y; asm("ex2.approx.f32 %0, %1;" : "=f"(y) : "f"(x)); return y;
}
__device__ __forceinline__ float rcpf(float x) {
    float y; asm("rcp.approx.f32 %0, %1;" : "=f"(y) : "f"(x)); return y;
}
__device__ __forceinline__ float sigf(float x) {
    return rcpf(1.0f + ex2f(-1.4426950408889634f * x));
}
__device__ __forceinline__ float tanhf_(float x) {
    return fmaf(2.0f, rcpf(1.0f + ex2f(-2.8853900817779268f * x)), -1.0f);
}
__device__ __forceinline__ void mma_tf32(float* d, const uint32_t* a, const uint32_t* b) {
    asm volatile(
        "mma.sync.aligned.m16n8k8.row.col.f32.tf32.tf32.f32 "
        "{%0,%1,%2,%3}, {%4,%5,%6,%7}, {%8,%9}, {%0,%1,%2,%3};"
        : "+f"(d[0]), "+f"(d[1]), "+f"(d[2]), "+f"(d[3])
        : "r"(a[0]), "r"(a[1]), "r"(a[2]), "r"(a[3]), "r"(b[0]), "r"(b[1]));
}
__device__ __forceinline__ void cpa16(uint32_t dst, const uint32_t* src) {
    asm volatile("cp.async.cg.shared.global [%0], [%1], 16;" :: "r"(dst), "l"(src));
}
__device__ __forceinline__ void cp_commit() {
    asm volatile("cp.async.commit_group;" ::: "memory");
}
__device__ __forceinline__ void pf_l2(const void* p) {
    asm volatile("prefetch.global.L2 [%0];" :: "l"(p));
}

// ---------------- SMEM layout (100 KB -> 2 CTAs/SM) ----------------
#define SMEM_BIAS  0          // 640 floats = 2560 B
#define SMEM_MAPL  2560       // 64 ints
#define SMEM_MAPR  2816       // 64 ints
#define SMEM_A     4096       // 64x256 tf32 fragment-packed = 65536 B
#define SMEM_B0    69632      // 16 KB
#define SMEM_B1    86016      // 16 KB
#define SMEM_TOTAL 102400

// A pack byte offset (relative to SMEM_A) for element (r,k), r in [0,64)
__device__ __forceinline__ uint32_t a_off(int r, int k) {
    int mt = r >> 4, kk = k >> 3;
    int lane = ((r & 7) << 2) | (k & 3);
    int slot = ((r >> 3) & 1) | (((k >> 2) & 1) << 1);
    return (uint32_t)((((mt << 5) + kk) << 5) + (lane ^ (kk & 7))) * 16u + (uint32_t)slot * 4u;
}

// ---------------- single merged prep kernel ----------------
__global__ void prep_all(const float* __restrict__ W,
                         const int* __restrict__ bf0, const int* __restrict__ bt0,
                         const int* __restrict__ pf0, const int* __restrict__ pt0,
                         const int* __restrict__ bf1, const int* __restrict__ bt1,
                         const int* __restrict__ pf1, const int* __restrict__ pt1) {
    int idx = blockIdx.x * blockDim.x + threadIdx.x;
    if (idx < KHALF) {
        g_rowmap_l[bt0[idx]] = bf0[idx];
        g_rowmap_l[pt0[idx]] = (int)((uint32_t)pf0[idx] | 0x80000000u);
        g_rowmap_r[bt1[idx]] = bf1[idx];
        g_rowmap_r[pt1[idx]] = (int)((uint32_t)pf1[idx] | 0x80000000u);
    }
    if (idx < 256 * 640) {
        int k = idx / 640, col = idx % 640;
        int gate = col >> 7, n = col & 127;     // gates: 0:i 1:o 2:u 3:f_l 4:f_r
        int pass, slot;
        if      (gate == 0) { pass = 0; slot = 0; }
        else if (gate == 2) { pass = 0; slot = 1; }
        else if (gate == 3) { pass = 1; slot = 0; }
        else if (gate == 4) { pass = 1; slot = 1; }
        else                { pass = 2; slot = 0; }
        int nt = n >> 3, nl = n & 7;
        int kl = k & 7;
        int lane = (nl << 2) | (kl & 3);
        int ws = (kl >> 2) & 1;
        int off;
        if (pass < 2) {  // K-chunk 16, 2 slots of 2048 words
            int chunk = k >> 4, kk = (k >> 3) & 1;
            off = pass * 65536 + chunk * 4096 + slot * 2048
                + ((kk * 8 + (nt >> 1)) * 32 + lane) * 4 + (nt & 1) * 2 + ws;
        } else {         // K-chunk 32, 1 slot of 4096 words
            int chunk = k >> 5, kk = (k >> 3) & 3;
            off = 131072 + chunk * 4096
                + ((kk * 8 + (nt >> 1)) * 32 + lane) * 4 + (nt & 1) * 2 + ws;
        }
        g_Bpack[off] = f2tf32(W[idx]);
    }
}

// ---------------- pipelined MMA pass ----------------
// one 16 KB chunk = 4096 words = 1024 x 16B units
__device__ __forceinline__ void issue_chunk16(uint32_t sdst, const uint32_t* src, int tid) {
    #pragma unroll
    for (int i = 0; i < 4; i++) {
        int unit = i * 256 + tid;
        cpa16(sdst + (uint32_t)unit * 16u, src + unit * 4);
    }
    cp_commit();
}

// Single-sync double-buffered pass.
// Invariant: chunk0 of this pass is already in-flight to B0 (preload or prior
// pass's cross-prefetch), with exactly one cp.async group pending at entry.
// Each iteration: wait chunk c -> one sync -> issue c+1 (other buffer) -> compute c.
// Safe with one sync: every warp's compute-of-c precedes its sync at c+1, which
// precedes the issue that overwrites c's buffer (at c+2).
template<int NS, int NCH, int KS>
__device__ __forceinline__ void run_pass(const uint32_t* __restrict__ gW,
                                         const uint32_t* __restrict__ nextW,
                                         char* smem, uint32_t sbase,
                                         int tid, int wm, int wq, int lane,
                                         float acc[][2][4][4]) {
    #pragma unroll
    for (int s = 0; s < NS; s++)
        #pragma unroll
        for (int mi = 0; mi < 2; mi++)
            #pragma unroll
            for (int ni = 0; ni < 4; ni++)
                #pragma unroll
                for (int c = 0; c < 4; c++) acc[s][mi][ni][c] = 0.0f;

    #pragma unroll 1
    for (int c = 0; c < NCH; c++) {
        asm volatile("cp.async.wait_group 0;" ::: "memory");   // chunk c landed
        __syncthreads();                                        // visible to all; prev compute done
        if (c < NCH - 1)
            issue_chunk16(sbase + ((c & 1) ? SMEM_B0 : SMEM_B1), gW + (c + 1) * 4096, tid);
        else if (nextW)
            issue_chunk16(sbase + ((c & 1) ? SMEM_B0 : SMEM_B1), nextW, tid);
        const char* bb = smem + ((c & 1) ? SMEM_B1 : SMEM_B0);

        #pragma unroll
        for (int kk = 0; kk < KS; kk++) {
            const int kkg = c * KS + kk;
            uint32_t a[2][4];
            #pragma unroll
            for (int mi = 0; mi < 2; mi++) {
                uint4 v = *(const uint4*)(smem + SMEM_A +
                    (uint32_t)((((wm * 2 + mi) * 32 + kkg) * 32) + (lane ^ (kkg & 7))) * 16u);
                a[mi][0] = v.x; a[mi][1] = v.y; a[mi][2] = v.z; a[mi][3] = v.w;
            }
            uint32_t b[NS][4][2];
            #pragma unroll
            for (int s = 0; s < NS; s++)
                #pragma unroll
                for (int np2 = 0; np2 < 2; np2++) {
                    uint4 v = *(const uint4*)(bb + s * 8192 +
                        (uint32_t)(((kk * 8 + wq * 2 + np2) * 32) + lane) * 16u);
                    b[s][np2 * 2][0]     = v.x; b[s][np2 * 2][1]     = v.y;
                    b[s][np2 * 2 + 1][0] = v.z; b[s][np2 * 2 + 1][1] = v.w;
                }
            #pragma unroll
            for (int s = 0; s < NS; s++)
                #pragma unroll
                for (int mi = 0; mi < 2; mi++)
                    #pragma unroll
                    for (int ni = 0; ni < 4; ni++)
                        mma_tf32(acc[s][mi][ni], a[mi], b[s][ni]);
        }
    }
}

// ---------------- main fused kernel ----------------
__global__ void __launch_bounds__(256, 2) treelstm_main(
    const float* __restrict__ h_bot, const float* __restrict__ c_bot,
    const float* __restrict__ h_buf, const float* __restrict__ c_buf,
    const float* __restrict__ bias,  float* __restrict__ out) {
    extern __shared__ char smem[];
    const uint32_t sbase = smem_u32(smem);
    float* bias_s = (float*)(smem + SMEM_BIAS);
    int*   mapl_s = (int*)(smem + SMEM_MAPL);
    int*   mapr_s = (int*)(smem + SMEM_MAPR);

    const int tid = threadIdx.x, wid = tid >> 5, lane = tid & 31;
    const int g = lane >> 2, tig = lane & 3;
    const int wm = wid & 1, wq = wid >> 1;
    const int blk = blockIdx.x;

    // preload pass0 chunk0 so its latency hides under the A gather
    issue_chunk16(sbase + SMEM_B0, g_Bpack, tid);

    for (int t = tid; t < 640; t += 256) bias_s[t] = bias[t];
    if (tid < 64) {
        mapl_s[tid] = g_rowmap_l[blk * 64 + tid];
        mapr_s[tid] = g_rowmap_r[blk * 64 + tid];
    }

    // ---- gather X = [h_l | h_r] into fragment-packed A (tf32) ----
    for (int j = wid; j < 128; j += 8) {
        int src = j & 1, r = j >> 1;
        int m = blk * 64 + r;
        int map = src ? g_rowmap_r[m] : g_rowmap_l[m];
        const float* sp = ((map < 0) ? h_buf : h_bot) + (size_t)(uint32_t)(map & 0x7fffffff) * DDIM;
        float4 v = ((const float4*)sp)[lane];
        int k0 = src * 128 + lane * 4;
        char* ab = smem + SMEM_A;
        *(uint32_t*)(ab + a_off(r, k0 + 0)) = f2tf32(v.x);
        *(uint32_t*)(ab + a_off(r, k0 + 1)) = f2tf32(v.y);
        *(uint32_t*)(ab + a_off(r, k0 + 2)) = f2tf32(v.z);
        *(uint32_t*)(ab + a_off(r, k0 + 3)) = f2tf32(v.w);
    }

    float acc[2][2][4][4];
    float creg[2][4][4];

    // ---- pass 0: gates i & u ----
    run_pass<2, 16, 2>(g_Bpack, g_Bpack + 65536, smem, sbase, tid, wm, wq, lane, acc);
    #pragma unroll
    for (int mi = 0; mi < 2; mi++)
        #pragma unroll
        for (int ni = 0; ni < 4; ni++) {
            int colg = wq * 32 + ni * 8 + tig * 2;
            float2 bi = *(const float2*)(bias_s + colg);         // i: cols 0..127
            float2 bu = *(const float2*)(bias_s + 256 + colg);   // u: cols 256..383
            creg[mi][ni][0] = sigf(acc[0][mi][ni][0] + bi.x) * tanhf_(acc[1][mi][ni][0] + bu.x);
            creg[mi][ni][1] = sigf(acc[0][mi][ni][1] + bi.y) * tanhf_(acc[1][mi][ni][1] + bu.y);
            creg[mi][ni][2] = sigf(acc[0][mi][ni][2] + bi.x) * tanhf_(acc[1][mi][ni][2] + bu.x);
            creg[mi][ni][3] = sigf(acc[0][mi][ni][3] + bi.y) * tanhf_(acc[1][mi][ni][3] + bu.y);
        }

    // ---- L2-prefetch the c_l/c_r rows this thread will gather after pass 1 ----
    {
        const int colb = wq * 32;
        #pragma unroll
        for (int mi = 0; mi < 2; mi++) {
            int row0 = wm * 32 + mi * 16 + g;
            int ml0 = mapl_s[row0], ml1 = mapl_s[row0 + 8];
            int mr0 = mapr_s[row0], mr1 = mapr_s[row0 + 8];
            pf_l2(((ml0 < 0) ? c_buf : c_bot) + (size_t)(uint32_t)(ml0 & 0x7fffffff) * DDIM + colb);
            pf_l2(((ml1 < 0) ? c_buf : c_bot) + (size_t)(uint32_t)(ml1 & 0x7fffffff) * DDIM + colb);
            pf_l2(((mr0 < 0) ? c_buf : c_bot) + (size_t)(uint32_t)(mr0 & 0x7fffffff) * DDIM + colb);
            pf_l2(((mr1 < 0) ? c_buf : c_bot) + (size_t)(uint32_t)(mr1 & 0x7fffffff) * DDIM + colb);
        }
    }

    // ---- pass 1: f_l & f_r together ----
    run_pass<2, 16, 2>(g_Bpack + 65536, g_Bpack + 131072, smem, sbase, tid, wm, wq, lane, acc);
    #pragma unroll
    for (int mi = 0; mi < 2; mi++) {
        int row0 = wm * 32 + mi * 16 + g;
        int ml0 = mapl_s[row0], ml1 = mapl_s[row0 + 8];
        int mr0 = mapr_s[row0], mr1 = mapr_s[row0 + 8];
        const float* cl0 = ((ml0 < 0) ? c_buf : c_bot) + (size_t)(uint32_t)(ml0 & 0x7fffffff) * DDIM;
        const float* cl1 = ((ml1 < 0) ? c_buf : c_bot) + (size_t)(uint32_t)(ml1 & 0x7fffffff) * DDIM;
        const float* cr0 = ((mr0 < 0) ? c_buf : c_bot) + (size_t)(uint32_t)(mr0 & 0x7fffffff) * DDIM;
        const float* cr1 = ((mr1 < 0) ? c_buf : c_bot) + (size_t)(uint32_t)(mr1 & 0x7fffffff) * DDIM;
        #pragma unroll
        for (int ni = 0; ni < 4; ni++) {
            int colg = wq * 32 + ni * 8 + tig * 2;
            float2 bl = *(const float2*)(bias_s + 384 + colg);   // f_l
            float2 br = *(const float2*)(bias_s + 512 + colg);   // f_r
            float2 vl0 = *(const float2*)(cl0 + colg);
            float2 vl1 = *(const float2*)(cl1 + colg);
            float2 vr0 = *(const float2*)(cr0 + colg);
            float2 vr1 = *(const float2*)(cr1 + colg);
            creg[mi][ni][0] = fmaf(sigf(acc[0][mi][ni][0] + bl.x), vl0.x, creg[mi][ni][0]);
            creg[mi][ni][1] = fmaf(sigf(acc[0][mi][ni][1] + bl.y), vl0.y, creg[mi][ni][1]);
            creg[mi][ni][2] = fmaf(sigf(acc[0][mi][ni][2] + bl.x), vl1.x, creg[mi][ni][2]);
            creg[mi][ni][3] = fmaf(sigf(acc[0][mi][ni][3] + bl.y), vl1.y, creg[mi][ni][3]);
            creg[mi][ni][0] = fmaf(sigf(acc[1][mi][ni][0] + br.x), vr0.x, creg[mi][ni][0]);
            creg[mi][ni][1] = fmaf(sigf(acc[1][mi][ni][1] + br.y), vr0.y, creg[mi][ni][1]);
            creg[mi][ni][2] = fmaf(sigf(acc[1][mi][ni][2] + br.x), vr1.x, creg[mi][ni][2]);
            creg[mi][ni][3] = fmaf(sigf(acc[1][mi][ni][3] + br.y), vr1.y, creg[mi][ni][3]);
        }
    }

    // ---- pass 2: o -> finalize h, c ----
    run_pass<1, 8, 4>(g_Bpack + 131072, nullptr, smem, sbase, tid, wm, wq, lane, acc);
    #pragma unroll
    for (int mi = 0; mi < 2; mi++) {
        int row0 = wm * 32 + mi * 16 + g;
        size_t m0 = (size_t)(blk * 64 + row0);
        size_t m1 = m0 + 8;
        #pragma unroll
        for (int ni = 0; ni < 4; ni++) {
            int colg = wq * 32 + ni * 8 + tig * 2;
            float2 bo = *(const float2*)(bias_s + 128 + colg);   // o: cols 128..255
            float2 h0, h1, c0, c1;
            c0.x = creg[mi][ni][0]; h0.x = sigf(acc[0][mi][ni][0] + bo.x) * tanhf_(c0.x);
            c0.y = creg[mi][ni][1]; h0.y = sigf(acc[0][mi][ni][1] + bo.y) * tanhf_(c0.y);
            c1.x = creg[mi][ni][2]; h1.x = sigf(acc[0][mi][ni][2] + bo.x) * tanhf_(c1.x);
            c1.y = creg[mi][ni][3]; h1.y = sigf(acc[0][mi][ni][3] + bo.y) * tanhf_(c1.y);
            *(float2*)(out + m0 * DDIM + colg) = h0;
            *(float2*)(out + m1 * DDIM + colg) = h1;
            *(float2*)(out + (size_t)MROWS * DDIM + m0 * DDIM + colg) = c0;
            *(float2*)(out + (size_t)MROWS * DDIM + m1 * DDIM + colg) = c1;
        }
    }
}

// ---------------- launch ----------------
extern "C" void kernel_launch(void* const* d_in, const int* in_sizes, int n_in,
                              void* d_out, int out_size) {
    const float* h_bot = (const float*)d_in[0];
    const float* c_bot = (const float*)d_in[1];
    const float* h_buf = (const float*)d_in[2];
    const float* c_buf = (const float*)d_in[3];
    const float* W     = (const float*)d_in[4];
    const float* b     = (const float*)d_in[5];
    const int* bf0 = (const int*)d_in[6];
    const int* bt0 = (const int*)d_in[7];
    const int* pf0 = (const int*)d_in[8];
    const int* pt0 = (const int*)d_in[9];
    const int* bf1 = (const int*)d_in[10];
    const int* bt1 = (const int*)d_in[11];
    const int* pf1 = (const int*)d_in[12];
    const int* pt1 = (const int*)d_in[13];
    float* out = (float*)d_out;

    cudaFuncSetAttribute(treelstm_main, cudaFuncAttributeMaxDynamicSharedMemorySize, SMEM_TOTAL);

    prep_all<<<640, 256>>>(W, bf0, bt0, pf0, pt0, bf1, bt1, pf1, pt1);
    treelstm_main<<<MROWS / 64, 256, SMEM_TOTAL>>>(h_bot, c_bot, h_buf, c_buf, b, out);
}